// round 11
// baseline (speedup 1.0000x reference)
#include <cuda_runtime.h>
#include <cuda_bf16.h>
#include <math.h>
#include <stdint.h>

// Problem constants
#define Bq    8
#define Tq    1500
#define Hq    1280
#define Dq    1279
#define Mq    375
#define OUTq  4096
#define MPAD  3072
#define ROWS  (Bq*Mq)       // 3000

// GEMM tiling
#define BK        32
#define KSTAGES   (Hq/BK)          // 40
#define SW        20               // smem row stride in words (40 bf16 = 32 data + 8 pad)
#define TEN_WORDS (128*SW)         // words per tensor tile (2560)
#define BUF_WORDS (4*TEN_WORDS)    // words per stage buffer (4 tensors)
#define NSTAGE    3
#define SMEM_GEMM (NSTAGE*BUF_WORDS*4)  // bytes (122880)

// ---------------- scratch (device globals: allocation-free) ----------------
__device__ float g_alphas[Bq*Tq];
__device__ int   g_pair_t[Bq*2*Tq];
__device__ float g_pair_w[Bq*2*Tq];
__device__ int   g_off[Bq*(Mq+1)];

__device__ __align__(128) __nv_bfloat16 g_Ahi [MPAD*Hq];
__device__ __align__(128) __nv_bfloat16 g_Alo [MPAD*Hq];
__device__ __align__(128) float         g_t1  [MPAD*Hq];
__device__ __align__(128) __nv_bfloat16 g_H2hi[MPAD*Hq];
__device__ __align__(128) __nv_bfloat16 g_H2lo[MPAD*Hq];
__device__ __align__(128) __nv_bfloat16 g_W1hi[Hq*Hq];
__device__ __align__(128) __nv_bfloat16 g_W1lo[Hq*Hq];
__device__ __align__(128) __nv_bfloat16 g_W2hi[OUTq*Hq];
__device__ __align__(128) __nv_bfloat16 g_W2lo[OUTq*Hq];

// ---------------- helpers ----------------------------------------------------
__device__ __forceinline__ uint32_t smem_u32(const void* p) {
    uint32_t a;
    asm("{ .reg .u64 t; cvta.to.shared.u64 t, %1; cvt.u32.u64 %0, t; }" : "=r"(a) : "l"(p));
    return a;
}
#define CP_ASYNC16(dst_u32, src_ptr) \
    asm volatile("cp.async.cg.shared.global [%0], [%1], 16;" \
        :: "r"(dst_u32), "l"(src_ptr) : "memory")
#define CP_COMMIT() asm volatile("cp.async.commit_group;" ::: "memory")
#define CP_WAIT0()  asm volatile("cp.async.wait_group 0;" ::: "memory")
#define CP_WAIT1()  asm volatile("cp.async.wait_group 1;" ::: "memory")

#define LDSM_X4(r0,r1,r2,r3, addr) \
    asm volatile("ldmatrix.sync.aligned.m8n8.x4.shared.b16 {%0,%1,%2,%3}, [%4];" \
        : "=r"(r0), "=r"(r1), "=r"(r2), "=r"(r3) : "r"(addr))

__device__ __forceinline__ void mma16816(float* c, const uint32_t* a, const uint32_t* b) {
    asm volatile(
        "mma.sync.aligned.m16n8k16.row.col.f32.bf16.bf16.f32 "
        "{%0,%1,%2,%3}, {%4,%5,%6,%7}, {%8,%9}, {%0,%1,%2,%3};"
        : "+f"(c[0]), "+f"(c[1]), "+f"(c[2]), "+f"(c[3])
        : "r"(a[0]), "r"(a[1]), "r"(a[2]), "r"(a[3]), "r"(b[0]), "r"(b[1]));
}

__device__ __forceinline__ void split_bf16(float x, __nv_bfloat16& h, __nv_bfloat16& l) {
    h = __float2bfloat16(x);
    l = __float2bfloat16(x - __bfloat162float(h));
}

// ---------------- K0: sigmoid, pred_num_tokens, scaled alphas ---------------
__global__ void __launch_bounds__(512) alpha_kernel(
    const float* __restrict__ af, const int* __restrict__ nt,
    float* __restrict__ out, int pred_off)
{
    int b = blockIdx.x, tid = threadIdx.x;
    float sg[3];
    float sum = 0.f;
#pragma unroll
    for (int i = 0; i < 3; i++) {
        int t = tid + i*512;
        if (t < Tq) {
            float x = af[((size_t)b*Tq + t)*Hq + (Hq-1)];
            float s = 1.f / (1.f + expf(-x));
            sg[i] = s; sum += s;
        } else sg[i] = 0.f;
    }
    __shared__ float red[16];
    __shared__ float s_scale;
#pragma unroll
    for (int o = 16; o; o >>= 1) sum += __shfl_xor_sync(0xffffffffu, sum, o);
    if ((tid & 31) == 0) red[tid >> 5] = sum;
    __syncthreads();
    if (tid == 0) {
        float tot = 0.f;
#pragma unroll
        for (int i = 0; i < 16; i++) tot += red[i];
        out[pred_off + b] = tot;
        s_scale = (float)nt[b] / tot;
    }
    __syncthreads();
    float sc = s_scale;
#pragma unroll
    for (int i = 0; i < 3; i++) {
        int t = tid + i*512;
        if (t < Tq) g_alphas[b*Tq + t] = sg[i] * sc;
    }
}

// ---------------- K1: serial CIF scan (1 thread per batch) ------------------
__global__ void __launch_bounds__(256) cif_scan_kernel(const int* __restrict__ nt)
{
    __shared__ float sal[Bq*Tq];
    int tid = threadIdx.x;
    for (int i = tid; i < Bq*Tq; i += 256) sal[i] = g_alphas[i];
    __syncthreads();
    if (tid >= Bq) return;
    int b = tid;
    const float* al = sal + b*Tq;
    int*   pt  = g_pair_t + b*2*Tq;
    float* pw  = g_pair_w + b*2*Tq;
    int*   off = g_off    + b*(Mq+1);
    int nm1 = nt[b] - 1;
    float integrate = 0.f;
    int m = 0, cnt = 0;
    off[0] = 0;
    for (int t = 0; t < Tq; t++) {
        float alpha = al[t];
        float need  = 1.f - integrate;
        integrate  += alpha;
        if (integrate >= 1.f) {
            pt[cnt] = t; pw[cnt] = need; cnt++;
            float rem = alpha - need;
            integrate -= 1.f;
            if (m < nm1) { off[m+1] = cnt; m++; }
            if (t < Tq-1) { pt[cnt] = t; pw[cnt] = rem; cnt++; }
        } else {
            pt[cnt] = t; pw[cnt] = alpha; cnt++;
        }
    }
    for (int mm = m+1; mm <= Mq; mm++) off[mm] = cnt;
}

// ---------------- K2: gather -> hi/lo bf16 ----------------------------------
__global__ void __launch_bounds__(256) gather_kernel(const float* __restrict__ af)
{
    int r = blockIdx.x;
    int b = r / Mq, m = r % Mq;
    int tid = threadIdx.x;
    int s = g_off[b*(Mq+1) + m];
    int e = g_off[b*(Mq+1) + m + 1];
    float acc[5] = {0.f, 0.f, 0.f, 0.f, 0.f};
    for (int p = s; p < e; p++) {
        int   t = g_pair_t[b*2*Tq + p];
        float w = g_pair_w[b*2*Tq + p];
        const float* row = af + ((size_t)b*Tq + t)*Hq;
#pragma unroll
        for (int i = 0; i < 5; i++) {
            int d = tid + i*256;
            if (d < Dq) acc[i] = fmaf(w, row[d], acc[i]);
        }
    }
#pragma unroll
    for (int i = 0; i < 5; i++) {
        int d = tid + i*256;
        float x = (d < Dq) ? acc[i] : 0.f;
        __nv_bfloat16 h, l; split_bf16(x, h, l);
        g_Ahi[(size_t)r*Hq + d] = h;
        g_Alo[(size_t)r*Hq + d] = l;
    }
}

// ---------------- K3: transpose + split weights -> [N][1280] bf16 -----------
__global__ void convw_kernel(const float* __restrict__ W,
                             __nv_bfloat16* __restrict__ hi,
                             __nv_bfloat16* __restrict__ lo, int K, int N)
{
    __shared__ float t[32][33];
    int n0 = blockIdx.x*32, k0 = blockIdx.y*32;
    int tx = threadIdx.x, ty = threadIdx.y;
#pragma unroll
    for (int j = 0; j < 32; j += 8) {
        int k = k0 + ty + j;
        t[ty+j][tx] = (k < K) ? W[(size_t)k*N + n0 + tx] : 0.f;
    }
    __syncthreads();
#pragma unroll
    for (int j = 0; j < 32; j += 8) {
        int n = n0 + ty + j;
        float x = t[tx][ty+j];
        __nv_bfloat16 h, l; split_bf16(x, h, l);
        hi[(size_t)n*Hq + k0 + tx] = h;
        lo[(size_t)n*Hq + k0 + tx] = l;
    }
}

// ---------------- warp-MMA GEMM: C[M,N] = A * B^T + bias --------------------
// Block 128x128, 8 warps (2Mx4N, warp tile 64x32), BK=32, 3-stage cp.async
// ring (wait_group 1), ldmatrix.x4 loads, split-bf16 (3 MMAs per tile pair).
__global__ void __launch_bounds__(256, 1) gemm_kernel(
    const __nv_bfloat16* __restrict__ Ahi, const __nv_bfloat16* __restrict__ Alo,
    const __nv_bfloat16* __restrict__ Bhi, const __nv_bfloat16* __restrict__ Blo,
    const float* __restrict__ bias, float* __restrict__ C,
    int N, int Mstore)
{
    extern __shared__ uint32_t sm[];      // [NSTAGE][4][TEN_WORDS]
    const int tid = threadIdx.x;
    const int lane = tid & 31, w = tid >> 5;
    const int wm = w >> 2, wn = w & 3;    // wm:0-1 (64 rows), wn:0-3 (32 cols)
    const int m0 = blockIdx.y * 128, n0 = blockIdx.x * 128;
    const uint32_t sbase = smem_u32(sm);

    // ---- cp.async: 8 chunks/thread/stage; tensor ten, chunk c = j*256+tid
    const __nv_bfloat16* gten[4] = { Ahi + (size_t)m0*Hq, Alo + (size_t)m0*Hq,
                                     Bhi + (size_t)n0*Hq, Blo + (size_t)n0*Hq };
    const __nv_bfloat16* gsrc[8];
    uint32_t sdst[NSTAGE][8];
#pragma unroll
    for (int ten = 0; ten < 4; ten++)
#pragma unroll
        for (int j = 0; j < 2; j++) {
            int c = j*256 + tid;
            int row = c >> 2, ch = c & 3;
            gsrc[ten*2+j] = gten[ten] + (size_t)row*Hq + ch*8;
            uint32_t off = (ten*TEN_WORDS + row*SW + ch*4) * 4;
#pragma unroll
            for (int bf = 0; bf < NSTAGE; bf++)
                sdst[bf][ten*2+j] = sbase + bf*(BUF_WORDS*4) + off;
        }

    // ---- ldmatrix per-lane addresses
    const int a_row = wm*64 + (lane & 15);
    const int a_k8  = (lane >> 4);               // 0/1 -> +16 bytes
    uint32_t aAddrHi = sbase + (0*TEN_WORDS + a_row*SW)*4 + a_k8*16;
    uint32_t aAddrLo = sbase + (1*TEN_WORDS + a_row*SW)*4 + a_k8*16;
    const int b_n  = wn*32 + (lane & 7) + ((lane >> 4) & 1)*8;
    const int b_k8 = (lane >> 3) & 1;
    uint32_t bAddrHi = sbase + (2*TEN_WORDS + b_n*SW)*4 + b_k8*16;
    uint32_t bAddrLo = sbase + (3*TEN_WORDS + b_n*SW)*4 + b_k8*16;

    float acc[4][4][4];
#pragma unroll
    for (int mt = 0; mt < 4; mt++)
#pragma unroll
        for (int nt = 0; nt < 4; nt++)
#pragma unroll
            for (int i = 0; i < 4; i++) acc[mt][nt][i] = 0.f;

    // prologue: stages 0 and 1 in flight
#pragma unroll
    for (int i = 0; i < 8; i++) CP_ASYNC16(sdst[0][i], gsrc[i]);
    CP_COMMIT();
#pragma unroll
    for (int i = 0; i < 8; i++) CP_ASYNC16(sdst[1][i], gsrc[i] + BK);
    CP_COMMIT();

    int buf = 0;
    for (int s = 0; s < KSTAGES; s++) {
        const uint32_t bofs = buf * (BUF_WORDS*4);
        if (s + 1 < KSTAGES) { CP_WAIT1(); } else { CP_WAIT0(); }
        __syncthreads();     // all threads done reading buf (s-1)%3 == (s+2)%3
        if (s + 2 < KSTAGES) {
            int pbuf = buf + 2; if (pbuf >= NSTAGE) pbuf -= NSTAGE;
#pragma unroll
            for (int i = 0; i < 8; i++)
                CP_ASYNC16(sdst[pbuf][i], gsrc[i] + (size_t)(s+2)*BK);
            CP_COMMIT();
        }
#pragma unroll
        for (int kk = 0; kk < 2; kk++) {
            const uint32_t kofs = bofs + kk*32;    // 16 bf16 = 32 bytes per kstep
            uint32_t ah[4][4], al[4][4], bh[8], bl[8];
#pragma unroll
            for (int mt = 0; mt < 4; mt++) {
                uint32_t adr = aAddrHi + kofs + mt*(16*SW*4);
                LDSM_X4(ah[mt][0], ah[mt][1], ah[mt][2], ah[mt][3], adr);
                uint32_t adr2 = aAddrLo + kofs + mt*(16*SW*4);
                LDSM_X4(al[mt][0], al[mt][1], al[mt][2], al[mt][3], adr2);
            }
#pragma unroll
            for (int np = 0; np < 2; np++) {
                uint32_t adr = bAddrHi + kofs + np*(16*SW*4);
                LDSM_X4(bh[np*4+0], bh[np*4+1], bh[np*4+2], bh[np*4+3], adr);
                uint32_t adr2 = bAddrLo + kofs + np*(16*SW*4);
                LDSM_X4(bl[np*4+0], bl[np*4+1], bl[np*4+2], bl[np*4+3], adr2);
            }
#pragma unroll
            for (int mt = 0; mt < 4; mt++)
#pragma unroll
                for (int nt = 0; nt < 4; nt++) {
                    mma16816(acc[mt][nt], ah[mt], &bh[nt*2]);
                    mma16816(acc[mt][nt], ah[mt], &bl[nt*2]);
                    mma16816(acc[mt][nt], al[mt], &bh[nt*2]);
                }
        }
        if (++buf >= NSTAGE) buf = 0;
    }

    // epilogue: row lane/4 (+8), col (lane%4)*2 (+1), add bias
    const int r4 = lane >> 2, c4 = lane & 3;
#pragma unroll
    for (int mt = 0; mt < 4; mt++) {
        int row = m0 + wm*64 + mt*16 + r4;
#pragma unroll
        for (int nt = 0; nt < 4; nt++) {
            int col = n0 + wn*32 + nt*8 + c4*2;
            float bx = bias[col], by = bias[col+1];
            if (row < Mstore) {
                float2 v = make_float2(acc[mt][nt][0] + bx, acc[mt][nt][1] + by);
                *(float2*)(C + (size_t)row*N + col) = v;
            }
            if (row + 8 < Mstore) {
                float2 v = make_float2(acc[mt][nt][2] + bx, acc[mt][nt][3] + by);
                *(float2*)(C + (size_t)(row+8)*N + col) = v;
            }
        }
    }
}

// ---------------- K5: RMSNorm rows of g_t1 -> hi/lo bf16 --------------------
__global__ void __launch_bounds__(256) rmsnorm_kernel(const float* __restrict__ w)
{
    int r = blockIdx.x, tid = threadIdx.x;
    const float* x = g_t1 + (size_t)r*Hq;
    float v[5];
    float ss = 0.f;
#pragma unroll
    for (int i = 0; i < 5; i++) {
        v[i] = x[tid + i*256];
        ss = fmaf(v[i], v[i], ss);
    }
    __shared__ float red[8];
    __shared__ float s_inv;
#pragma unroll
    for (int o = 16; o; o >>= 1) ss += __shfl_xor_sync(0xffffffffu, ss, o);
    if ((tid & 31) == 0) red[tid >> 5] = ss;
    __syncthreads();
    if (tid == 0) {
        float tot = 0.f;
#pragma unroll
        for (int i = 0; i < 8; i++) tot += red[i];
        s_inv = 1.f / sqrtf(tot / (float)Hq + 1e-6f);
    }
    __syncthreads();
    float inv = s_inv;
#pragma unroll
    for (int i = 0; i < 5; i++) {
        int d = tid + i*256;
        float y = v[i] * inv * w[d];
        __nv_bfloat16 h, l; split_bf16(y, h, l);
        g_H2hi[(size_t)r*Hq + d] = h;
        g_H2lo[(size_t)r*Hq + d] = l;
    }
}

// ---------------- launch ----------------------------------------------------
extern "C" void kernel_launch(void* const* d_in, const int* in_sizes, int n_in,
                              void* d_out, int out_size)
{
    const float* af     = (const float*)d_in[0];
    const int*   nt     = (const int*)  d_in[1];
    const float* rms_w  = (const float*)d_in[2];
    const float* cif_w  = (const float*)d_in[3];
    const float* cif_b  = (const float*)d_in[4];
    const float* text_w = (const float*)d_in[5];
    const float* text_b = (const float*)d_in[6];
    float* out = (float*)d_out;
    int pred_off = out_size - Bq;

    __nv_bfloat16 *pAhi, *pAlo, *pH2hi, *pH2lo, *pW1hi, *pW1lo, *pW2hi, *pW2lo;
    float* pT1;
    cudaGetSymbolAddress((void**)&pAhi,  g_Ahi);
    cudaGetSymbolAddress((void**)&pAlo,  g_Alo);
    cudaGetSymbolAddress((void**)&pT1,   g_t1);
    cudaGetSymbolAddress((void**)&pH2hi, g_H2hi);
    cudaGetSymbolAddress((void**)&pH2lo, g_H2lo);
    cudaGetSymbolAddress((void**)&pW1hi, g_W1hi);
    cudaGetSymbolAddress((void**)&pW1lo, g_W1lo);
    cudaGetSymbolAddress((void**)&pW2hi, g_W2hi);
    cudaGetSymbolAddress((void**)&pW2lo, g_W2lo);

    cudaFuncSetAttribute(gemm_kernel,
                         cudaFuncAttributeMaxDynamicSharedMemorySize, SMEM_GEMM);

    alpha_kernel<<<Bq, 512>>>(af, nt, out, pred_off);
    cif_scan_kernel<<<1, 256>>>(nt);
    gather_kernel<<<ROWS, 256>>>(af);
    convw_kernel<<<dim3(Hq/32,   Hq/32), dim3(32,8)>>>(cif_w,  pW1hi, pW1lo, Dq, Hq);
    convw_kernel<<<dim3(OUTq/32, Hq/32), dim3(32,8)>>>(text_w, pW2hi, pW2lo, Hq, OUTq);
    // cif_proj: [3072,1280] x [1280,1280]^T + cif_b -> t1 (fp32, all MPAD rows)
    gemm_kernel<<<dim3(Hq/128, MPAD/128), 256, SMEM_GEMM>>>(
        pAhi, pAlo, pW1hi, pW1lo, cif_b, pT1, Hq, MPAD);
    rmsnorm_kernel<<<MPAD, 256>>>(rms_w);
    // text_proj: [3072,1280] x [4096,1280]^T + text_b -> out (rows < 3000)
    gemm_kernel<<<dim3(OUTq/128, MPAD/128), 256, SMEM_GEMM>>>(
        pH2hi, pH2lo, pW2hi, pW2lo, text_b, out, OUTq, ROWS);
}

// round 12
// speedup vs baseline: 1.0921x; 1.0921x over previous
#include <cuda_runtime.h>
#include <cuda_bf16.h>
#include <math.h>
#include <stdint.h>

// Problem constants
#define Bq    8
#define Tq    1500
#define Hq    1280
#define Dq    1279
#define Mq    375
#define OUTq  4096
#define MPAD  3072
#define ROWS  (Bq*Mq)       // 3000

// GEMM tiling: block 256x128, 8 warps (4M x 2N), warp tile 64x64, BK=32
#define BK        32
#define KSTAGES   (Hq/BK)          // 40
#define SW        20               // smem row stride in words (32 data bf16 + 8 pad)
#define AHI_W     0
#define ALO_W     (256*SW)         // 5120
#define BHI_W     (512*SW)         // 10240
#define BLO_W     (640*SW)         // 12800
#define STAGE_W   (768*SW)         // 15360 words
#define STAGE_B   (STAGE_W*4)      // 61440 bytes
#define SMEM_GEMM (2*STAGE_B)      // 122880 bytes

// ---------------- scratch (device globals: allocation-free) ----------------
__device__ float g_alphas[Bq*Tq];
__device__ int   g_pair_t[Bq*2*Tq];
__device__ float g_pair_w[Bq*2*Tq];
__device__ int   g_off[Bq*(Mq+1)];

__device__ __align__(128) __nv_bfloat16 g_Ahi [MPAD*Hq];
__device__ __align__(128) __nv_bfloat16 g_Alo [MPAD*Hq];
__device__ __align__(128) float         g_t1  [MPAD*Hq];
__device__ __align__(128) __nv_bfloat16 g_H2hi[MPAD*Hq];
__device__ __align__(128) __nv_bfloat16 g_H2lo[MPAD*Hq];
__device__ __align__(128) __nv_bfloat16 g_W1hi[Hq*Hq];
__device__ __align__(128) __nv_bfloat16 g_W1lo[Hq*Hq];
__device__ __align__(128) __nv_bfloat16 g_W2hi[OUTq*Hq];
__device__ __align__(128) __nv_bfloat16 g_W2lo[OUTq*Hq];

// ---------------- helpers ----------------------------------------------------
__device__ __forceinline__ uint32_t smem_u32(const void* p) {
    uint32_t a;
    asm("{ .reg .u64 t; cvta.to.shared.u64 t, %1; cvt.u32.u64 %0, t; }" : "=r"(a) : "l"(p));
    return a;
}
#define CP_ASYNC16(dst_u32, src_ptr) \
    asm volatile("cp.async.cg.shared.global [%0], [%1], 16;" \
        :: "r"(dst_u32), "l"(src_ptr) : "memory")
#define CP_COMMIT() asm volatile("cp.async.commit_group;" ::: "memory")
#define CP_WAIT0()  asm volatile("cp.async.wait_group 0;" ::: "memory")

#define LDSM_X4(r0,r1,r2,r3, addr) \
    asm volatile("ldmatrix.sync.aligned.m8n8.x4.shared.b16 {%0,%1,%2,%3}, [%4];" \
        : "=r"(r0), "=r"(r1), "=r"(r2), "=r"(r3) : "r"(addr))

__device__ __forceinline__ void mma16816(float* c, const uint32_t* a, const uint32_t* b) {
    asm volatile(
        "mma.sync.aligned.m16n8k16.row.col.f32.bf16.bf16.f32 "
        "{%0,%1,%2,%3}, {%4,%5,%6,%7}, {%8,%9}, {%0,%1,%2,%3};"
        : "+f"(c[0]), "+f"(c[1]), "+f"(c[2]), "+f"(c[3])
        : "r"(a[0]), "r"(a[1]), "r"(a[2]), "r"(a[3]), "r"(b[0]), "r"(b[1]));
}

__device__ __forceinline__ void split_bf16(float x, __nv_bfloat16& h, __nv_bfloat16& l) {
    h = __float2bfloat16(x);
    l = __float2bfloat16(x - __bfloat162float(h));
}

// ---------------- K0: sigmoid, pred_num_tokens, scaled alphas ---------------
__global__ void __launch_bounds__(512) alpha_kernel(
    const float* __restrict__ af, const int* __restrict__ nt,
    float* __restrict__ out, int pred_off)
{
    int b = blockIdx.x, tid = threadIdx.x;
    float sg[3];
    float sum = 0.f;
#pragma unroll
    for (int i = 0; i < 3; i++) {
        int t = tid + i*512;
        if (t < Tq) {
            float x = af[((size_t)b*Tq + t)*Hq + (Hq-1)];
            float s = 1.f / (1.f + expf(-x));
            sg[i] = s; sum += s;
        } else sg[i] = 0.f;
    }
    __shared__ float red[16];
    __shared__ float s_scale;
#pragma unroll
    for (int o = 16; o; o >>= 1) sum += __shfl_xor_sync(0xffffffffu, sum, o);
    if ((tid & 31) == 0) red[tid >> 5] = sum;
    __syncthreads();
    if (tid == 0) {
        float tot = 0.f;
#pragma unroll
        for (int i = 0; i < 16; i++) tot += red[i];
        out[pred_off + b] = tot;
        s_scale = (float)nt[b] / tot;
    }
    __syncthreads();
    float sc = s_scale;
#pragma unroll
    for (int i = 0; i < 3; i++) {
        int t = tid + i*512;
        if (t < Tq) g_alphas[b*Tq + t] = sg[i] * sc;
    }
}

// ---------------- K1: serial CIF scan (1 thread per batch) ------------------
__global__ void __launch_bounds__(256) cif_scan_kernel(const int* __restrict__ nt)
{
    __shared__ float sal[Bq*Tq];
    int tid = threadIdx.x;
    for (int i = tid; i < Bq*Tq; i += 256) sal[i] = g_alphas[i];
    __syncthreads();
    if (tid >= Bq) return;
    int b = tid;
    const float* al = sal + b*Tq;
    int*   pt  = g_pair_t + b*2*Tq;
    float* pw  = g_pair_w + b*2*Tq;
    int*   off = g_off    + b*(Mq+1);
    int nm1 = nt[b] - 1;
    float integrate = 0.f;
    int m = 0, cnt = 0;
    off[0] = 0;
    for (int t = 0; t < Tq; t++) {
        float alpha = al[t];
        float need  = 1.f - integrate;
        integrate  += alpha;
        if (integrate >= 1.f) {
            pt[cnt] = t; pw[cnt] = need; cnt++;
            float rem = alpha - need;
            integrate -= 1.f;
            if (m < nm1) { off[m+1] = cnt; m++; }
            if (t < Tq-1) { pt[cnt] = t; pw[cnt] = rem; cnt++; }
        } else {
            pt[cnt] = t; pw[cnt] = alpha; cnt++;
        }
    }
    for (int mm = m+1; mm <= Mq; mm++) off[mm] = cnt;
}

// ---------------- K2: gather -> hi/lo bf16 ----------------------------------
__global__ void __launch_bounds__(256) gather_kernel(const float* __restrict__ af)
{
    int r = blockIdx.x;
    int b = r / Mq, m = r % Mq;
    int tid = threadIdx.x;
    int s = g_off[b*(Mq+1) + m];
    int e = g_off[b*(Mq+1) + m + 1];
    float acc[5] = {0.f, 0.f, 0.f, 0.f, 0.f};
    for (int p = s; p < e; p++) {
        int   t = g_pair_t[b*2*Tq + p];
        float w = g_pair_w[b*2*Tq + p];
        const float* row = af + ((size_t)b*Tq + t)*Hq;
#pragma unroll
        for (int i = 0; i < 5; i++) {
            int d = tid + i*256;
            if (d < Dq) acc[i] = fmaf(w, row[d], acc[i]);
        }
    }
#pragma unroll
    for (int i = 0; i < 5; i++) {
        int d = tid + i*256;
        float x = (d < Dq) ? acc[i] : 0.f;
        __nv_bfloat16 h, l; split_bf16(x, h, l);
        g_Ahi[(size_t)r*Hq + d] = h;
        g_Alo[(size_t)r*Hq + d] = l;
    }
}

// ---------------- K3: transpose + split weights -> [N][1280] bf16 -----------
__global__ void convw_kernel(const float* __restrict__ W,
                             __nv_bfloat16* __restrict__ hi,
                             __nv_bfloat16* __restrict__ lo, int K, int N)
{
    __shared__ float t[32][33];
    int n0 = blockIdx.x*32, k0 = blockIdx.y*32;
    int tx = threadIdx.x, ty = threadIdx.y;
#pragma unroll
    for (int j = 0; j < 32; j += 8) {
        int k = k0 + ty + j;
        t[ty+j][tx] = (k < K) ? W[(size_t)k*N + n0 + tx] : 0.f;
    }
    __syncthreads();
#pragma unroll
    for (int j = 0; j < 32; j += 8) {
        int n = n0 + ty + j;
        float x = t[tx][ty+j];
        __nv_bfloat16 h, l; split_bf16(x, h, l);
        hi[(size_t)n*Hq + k0 + tx] = h;
        lo[(size_t)n*Hq + k0 + tx] = l;
    }
}

// ---------------- warp-MMA GEMM: C[M,N] = A * B^T + bias --------------------
// Block 256x128, 8 warps (4M x 2N, warp tile 64x64), BK=32, double-buffered
// cp.async, ldmatrix.x4 loads, split-bf16 (3 MMAs per tile pair).
__global__ void __launch_bounds__(256, 1) gemm_kernel(
    const __nv_bfloat16* __restrict__ Ahi, const __nv_bfloat16* __restrict__ Alo,
    const __nv_bfloat16* __restrict__ Bhi, const __nv_bfloat16* __restrict__ Blo,
    const float* __restrict__ bias, float* __restrict__ C,
    int N, int Mstore)
{
    extern __shared__ uint32_t sm[];      // [2][STAGE_W]
    const int tid = threadIdx.x;
    const int lane = tid & 31, w = tid >> 5;
    const int wm = w >> 1, wn = w & 1;    // wm:0-3 (64 rows each), wn:0-1 (64 cols)
    const int m0 = blockIdx.y * 256, n0 = blockIdx.x * 128;
    const uint32_t sbase = smem_u32(sm);

    // ---- cp.async: 12 chunks/thread/stage. Per thread: row=tid>>2 (0..63),
    // ch=tid&3. A tensors: 4 row-groups of 64; B tensors: 2 row-groups of 64.
    const int crow = tid >> 2, cch = tid & 3;
    const __nv_bfloat16* pA_h = Ahi + (size_t)(m0 + crow)*Hq + cch*8;
    const __nv_bfloat16* pA_l = Alo + (size_t)(m0 + crow)*Hq + cch*8;
    const __nv_bfloat16* pB_h = Bhi + (size_t)(n0 + crow)*Hq + cch*8;
    const __nv_bfloat16* pB_l = Blo + (size_t)(n0 + crow)*Hq + cch*8;
    const uint32_t drow = (crow*SW + cch*4)*4;   // byte offset of (row,ch)

    // ---- ldmatrix per-lane addresses
    const int a_row = wm*64 + (lane & 15);
    const int a_k8  = (lane >> 4);               // 0/1 -> +16 bytes
    const uint32_t aAddrHi = sbase + (AHI_W + a_row*SW)*4 + a_k8*16;
    const uint32_t aAddrLo = sbase + (ALO_W + a_row*SW)*4 + a_k8*16;
    const int b_n  = wn*64 + (lane & 7) + ((lane >> 4) & 1)*8;
    const int b_k8 = (lane >> 3) & 1;
    const uint32_t bAddrHi = sbase + (BHI_W + b_n*SW)*4 + b_k8*16;
    const uint32_t bAddrLo = sbase + (BLO_W + b_n*SW)*4 + b_k8*16;

    float acc[4][8][4];
#pragma unroll
    for (int mt = 0; mt < 4; mt++)
#pragma unroll
        for (int nt = 0; nt < 8; nt++)
#pragma unroll
            for (int i = 0; i < 4; i++) acc[mt][nt][i] = 0.f;

#define COPY_STAGE(kstg, bufofs) do {                                          \
    const size_t kb = (size_t)(kstg)*BK;                                       \
    _Pragma("unroll")                                                          \
    for (int j = 0; j < 4; j++)                                                \
        CP_ASYNC16(sbase + (bufofs) + AHI_W*4 + j*(64*SW*4) + drow,            \
                   pA_h + (size_t)j*64*Hq + kb);                               \
    _Pragma("unroll")                                                          \
    for (int j = 0; j < 4; j++)                                                \
        CP_ASYNC16(sbase + (bufofs) + ALO_W*4 + j*(64*SW*4) + drow,            \
                   pA_l + (size_t)j*64*Hq + kb);                               \
    _Pragma("unroll")                                                          \
    for (int j = 0; j < 2; j++)                                                \
        CP_ASYNC16(sbase + (bufofs) + BHI_W*4 + j*(64*SW*4) + drow,            \
                   pB_h + (size_t)j*64*Hq + kb);                               \
    _Pragma("unroll")                                                          \
    for (int j = 0; j < 2; j++)                                                \
        CP_ASYNC16(sbase + (bufofs) + BLO_W*4 + j*(64*SW*4) + drow,            \
                   pB_l + (size_t)j*64*Hq + kb);                               \
} while (0)

    // prologue: stage 0 -> buf 0
    COPY_STAGE(0, 0u);
    CP_COMMIT();

    for (int s = 0; s < KSTAGES; s++) {
        const int buf = s & 1;
        const uint32_t bofs = buf * STAGE_B;
        CP_WAIT0();
        __syncthreads();
        if (s + 1 < KSTAGES) {
            COPY_STAGE(s+1, (uint32_t)((buf^1) * STAGE_B));
            CP_COMMIT();
        }
#pragma unroll
        for (int kk = 0; kk < 2; kk++) {
            const uint32_t kofs = bofs + kk*32;    // 16 bf16 = 32 bytes per kstep
            uint32_t ah[4][4], al[4][4], bh[16], bl[16];
#pragma unroll
            for (int mt = 0; mt < 4; mt++) {
                LDSM_X4(ah[mt][0], ah[mt][1], ah[mt][2], ah[mt][3],
                        aAddrHi + kofs + mt*(16*SW*4));
                LDSM_X4(al[mt][0], al[mt][1], al[mt][2], al[mt][3],
                        aAddrLo + kofs + mt*(16*SW*4));
            }
#pragma unroll
            for (int np = 0; np < 4; np++) {
                LDSM_X4(bh[np*4+0], bh[np*4+1], bh[np*4+2], bh[np*4+3],
                        bAddrHi + kofs + np*(16*SW*4));
                LDSM_X4(bl[np*4+0], bl[np*4+1], bl[np*4+2], bl[np*4+3],
                        bAddrLo + kofs + np*(16*SW*4));
            }
#pragma unroll
            for (int mt = 0; mt < 4; mt++)
#pragma unroll
                for (int nt = 0; nt < 8; nt++) {
                    mma16816(acc[mt][nt], ah[mt], &bh[nt*2]);
                    mma16816(acc[mt][nt], ah[mt], &bl[nt*2]);
                    mma16816(acc[mt][nt], al[mt], &bh[nt*2]);
                }
        }
    }

    // epilogue: row lane/4 (+8), col (lane%4)*2 (+1), add bias
    const int r4 = lane >> 2, c4 = lane & 3;
#pragma unroll
    for (int mt = 0; mt < 4; mt++) {
        int row = m0 + wm*64 + mt*16 + r4;
#pragma unroll
        for (int nt = 0; nt < 8; nt++) {
            int col = n0 + wn*64 + nt*8 + c4*2;
            float bx = bias[col], by = bias[col+1];
            if (row < Mstore) {
                float2 v = make_float2(acc[mt][nt][0] + bx, acc[mt][nt][1] + by);
                *(float2*)(C + (size_t)row*N + col) = v;
            }
            if (row + 8 < Mstore) {
                float2 v = make_float2(acc[mt][nt][2] + bx, acc[mt][nt][3] + by);
                *(float2*)(C + (size_t)(row+8)*N + col) = v;
            }
        }
    }
}

// ---------------- K5: RMSNorm rows of g_t1 -> hi/lo bf16 --------------------
__global__ void __launch_bounds__(256) rmsnorm_kernel(const float* __restrict__ w)
{
    int r = blockIdx.x, tid = threadIdx.x;
    const float* x = g_t1 + (size_t)r*Hq;
    float v[5];
    float ss = 0.f;
#pragma unroll
    for (int i = 0; i < 5; i++) {
        v[i] = x[tid + i*256];
        ss = fmaf(v[i], v[i], ss);
    }
    __shared__ float red[8];
    __shared__ float s_inv;
#pragma unroll
    for (int o = 16; o; o >>= 1) ss += __shfl_xor_sync(0xffffffffu, ss, o);
    if ((tid & 31) == 0) red[tid >> 5] = ss;
    __syncthreads();
    if (tid == 0) {
        float tot = 0.f;
#pragma unroll
        for (int i = 0; i < 8; i++) tot += red[i];
        s_inv = 1.f / sqrtf(tot / (float)Hq + 1e-6f);
    }
    __syncthreads();
    float inv = s_inv;
#pragma unroll
    for (int i = 0; i < 5; i++) {
        int d = tid + i*256;
        float y = v[i] * inv * w[d];
        __nv_bfloat16 h, l; split_bf16(y, h, l);
        g_H2hi[(size_t)r*Hq + d] = h;
        g_H2lo[(size_t)r*Hq + d] = l;
    }
}

// ---------------- launch ----------------------------------------------------
extern "C" void kernel_launch(void* const* d_in, const int* in_sizes, int n_in,
                              void* d_out, int out_size)
{
    const float* af     = (const float*)d_in[0];
    const int*   nt     = (const int*)  d_in[1];
    const float* rms_w  = (const float*)d_in[2];
    const float* cif_w  = (const float*)d_in[3];
    const float* cif_b  = (const float*)d_in[4];
    const float* text_w = (const float*)d_in[5];
    const float* text_b = (const float*)d_in[6];
    float* out = (float*)d_out;
    int pred_off = out_size - Bq;

    __nv_bfloat16 *pAhi, *pAlo, *pH2hi, *pH2lo, *pW1hi, *pW1lo, *pW2hi, *pW2lo;
    float* pT1;
    cudaGetSymbolAddress((void**)&pAhi,  g_Ahi);
    cudaGetSymbolAddress((void**)&pAlo,  g_Alo);
    cudaGetSymbolAddress((void**)&pT1,   g_t1);
    cudaGetSymbolAddress((void**)&pH2hi, g_H2hi);
    cudaGetSymbolAddress((void**)&pH2lo, g_H2lo);
    cudaGetSymbolAddress((void**)&pW1hi, g_W1hi);
    cudaGetSymbolAddress((void**)&pW1lo, g_W1lo);
    cudaGetSymbolAddress((void**)&pW2hi, g_W2hi);
    cudaGetSymbolAddress((void**)&pW2lo, g_W2lo);

    cudaFuncSetAttribute(gemm_kernel,
                         cudaFuncAttributeMaxDynamicSharedMemorySize, SMEM_GEMM);

    // convw first (dependency-free) so ncu -s 5 lands on gemm_kernel
    convw_kernel<<<dim3(Hq/32,   Hq/32), dim3(32,8)>>>(cif_w,  pW1hi, pW1lo, Dq, Hq);
    convw_kernel<<<dim3(OUTq/32, Hq/32), dim3(32,8)>>>(text_w, pW2hi, pW2lo, Hq, OUTq);
    alpha_kernel<<<Bq, 512>>>(af, nt, out, pred_off);
    cif_scan_kernel<<<1, 256>>>(nt);
    gather_kernel<<<ROWS, 256>>>(af);
    // cif_proj: [3072,1280] x [1280,1280]^T + cif_b -> t1 (fp32, all MPAD rows)
    gemm_kernel<<<dim3(Hq/128, MPAD/256), 256, SMEM_GEMM>>>(
        pAhi, pAlo, pW1hi, pW1lo, cif_b, pT1, Hq, MPAD);
    rmsnorm_kernel<<<MPAD, 256>>>(rms_w);
    // text_proj: [3072,1280] x [4096,1280]^T + text_b -> out (rows < 3000)
    gemm_kernel<<<dim3(OUTq/128, MPAD/256), 256, SMEM_GEMM>>>(
        pH2hi, pH2lo, pW2hi, pW2lo, text_b, out, OUTq, ROWS);
}

// round 13
// speedup vs baseline: 1.3160x; 1.2050x over previous
#include <cuda_runtime.h>
#include <cuda_bf16.h>
#include <math.h>
#include <stdint.h>

// Problem constants
#define Bq    8
#define Tq    1500
#define Hq    1280
#define Dq    1279
#define Mq    375
#define OUTq  4096
#define MPAD  3072
#define ROWS  (Bq*Mq)       // 3000

// GEMM tiling: block 256x128, 8 warps (4M x 2N), warp tile 64x64, BK=32
#define BK        32
#define KSTAGES   (Hq/BK)          // 40
#define SW        20               // smem row stride in words (32 data bf16 + 8 pad)
#define AHI_W     0
#define ALO_W     (256*SW)         // 5120
#define BHI_W     (512*SW)         // 10240
#define BLO_W     (640*SW)         // 12800
#define STAGE_W   (768*SW)         // 15360 words
#define STAGE_B   (STAGE_W*4)      // 61440 bytes
#define SMEM_GEMM (2*STAGE_B)      // 122880 bytes

// ---------------- scratch (device globals: allocation-free) ----------------
__device__ float g_alphas[Bq*Tq];
__device__ int   g_pair_t[Bq*2*Tq];
__device__ float g_pair_w[Bq*2*Tq];
__device__ int   g_off[Bq*(Mq+1)];

__device__ __align__(128) __nv_bfloat16 g_Ahi [MPAD*Hq];
__device__ __align__(128) __nv_bfloat16 g_Alo [MPAD*Hq];
__device__ __align__(128) float         g_t1  [MPAD*Hq];
__device__ __align__(128) __nv_bfloat16 g_H2hi[MPAD*Hq];
__device__ __align__(128) __nv_bfloat16 g_H2lo[MPAD*Hq];
__device__ __align__(128) __nv_bfloat16 g_W1hi[Hq*Hq];
__device__ __align__(128) __nv_bfloat16 g_W1lo[Hq*Hq];
__device__ __align__(128) __nv_bfloat16 g_W2hi[OUTq*Hq];
__device__ __align__(128) __nv_bfloat16 g_W2lo[OUTq*Hq];

// ---------------- helpers ----------------------------------------------------
__device__ __forceinline__ uint32_t smem_u32(const void* p) {
    uint32_t a;
    asm("{ .reg .u64 t; cvta.to.shared.u64 t, %1; cvt.u32.u64 %0, t; }" : "=r"(a) : "l"(p));
    return a;
}
#define CP_ASYNC16(dst_u32, src_ptr) \
    asm volatile("cp.async.cg.shared.global [%0], [%1], 16;" \
        :: "r"(dst_u32), "l"(src_ptr) : "memory")
#define CP_COMMIT() asm volatile("cp.async.commit_group;" ::: "memory")
#define CP_WAIT0()  asm volatile("cp.async.wait_group 0;" ::: "memory")

#define LDSM_X4(r0,r1,r2,r3, addr) \
    asm volatile("ldmatrix.sync.aligned.m8n8.x4.shared.b16 {%0,%1,%2,%3}, [%4];" \
        : "=r"(r0), "=r"(r1), "=r"(r2), "=r"(r3) : "r"(addr))

__device__ __forceinline__ void mma16816(float* c, const uint32_t* a, const uint32_t* b) {
    asm volatile(
        "mma.sync.aligned.m16n8k16.row.col.f32.bf16.bf16.f32 "
        "{%0,%1,%2,%3}, {%4,%5,%6,%7}, {%8,%9}, {%0,%1,%2,%3};"
        : "+f"(c[0]), "+f"(c[1]), "+f"(c[2]), "+f"(c[3])
        : "r"(a[0]), "r"(a[1]), "r"(a[2]), "r"(a[3]), "r"(b[0]), "r"(b[1]));
}

__device__ __forceinline__ void split_bf16(float x, __nv_bfloat16& h, __nv_bfloat16& l) {
    h = __float2bfloat16(x);
    l = __float2bfloat16(x - __bfloat162float(h));
}

// ---------------- K0: sigmoid, pred_num_tokens, scaled alphas ---------------
__global__ void __launch_bounds__(512) alpha_kernel(
    const float* __restrict__ af, const int* __restrict__ nt,
    float* __restrict__ out, int pred_off)
{
    int b = blockIdx.x, tid = threadIdx.x;
    float sg[3];
    float sum = 0.f;
#pragma unroll
    for (int i = 0; i < 3; i++) {
        int t = tid + i*512;
        if (t < Tq) {
            float x = af[((size_t)b*Tq + t)*Hq + (Hq-1)];
            float s = 1.f / (1.f + expf(-x));
            sg[i] = s; sum += s;
        } else sg[i] = 0.f;
    }
    __shared__ float red[16];
    __shared__ float s_scale;
#pragma unroll
    for (int o = 16; o; o >>= 1) sum += __shfl_xor_sync(0xffffffffu, sum, o);
    if ((tid & 31) == 0) red[tid >> 5] = sum;
    __syncthreads();
    if (tid == 0) {
        float tot = 0.f;
#pragma unroll
        for (int i = 0; i < 16; i++) tot += red[i];
        out[pred_off + b] = tot;
        s_scale = (float)nt[b] / tot;
    }
    __syncthreads();
    float sc = s_scale;
#pragma unroll
    for (int i = 0; i < 3; i++) {
        int t = tid + i*512;
        if (t < Tq) g_alphas[b*Tq + t] = sg[i] * sc;
    }
}

// ---------------- K1: PARALLEL CIF scan (1 block per batch) ------------------
// Closed form: with all alpha<1, integrate_t = S_t - floor(S_t); fire at t iff
// floor(S_t) > floor(S_{t-1}); pair index p_t = t + floor(S_{t-1}); token =
// min(floor(S_{t-1}), nm1). Each thread owns 3 consecutive t (sequential within
// thread, block-scan for offsets).
__global__ void __launch_bounds__(512) cif_scan_kernel(const int* __restrict__ nt)
{
    int b = blockIdx.x, tid = threadIdx.x;
    int lane = tid & 31, wid = tid >> 5;
    int t0 = tid * 3;
    float a[3];
#pragma unroll
    for (int j = 0; j < 3; j++) {
        int t = t0 + j;
        a[j] = (t < Tq) ? g_alphas[b*Tq + t] : 0.f;
    }
    float tot = a[0] + a[1] + a[2];
    // warp inclusive scan of per-thread totals
    float inc = tot;
#pragma unroll
    for (int o = 1; o < 32; o <<= 1) {
        float v = __shfl_up_sync(0xffffffffu, inc, o);
        if (lane >= o) inc += v;
    }
    __shared__ float wsum[16];
    __shared__ float s_Sp_last, s_Sc_last;
    if (lane == 31) wsum[wid] = inc;
    __syncthreads();
    if (wid == 0) {
        float v = (lane < 16) ? wsum[lane] : 0.f;
#pragma unroll
        for (int o = 1; o < 16; o <<= 1) {
            float u = __shfl_up_sync(0xffffffffu, v, o);
            if (lane >= o) v += u;
        }
        if (lane < 16) wsum[lane] = v;
    }
    __syncthreads();
    float excl = inc - tot + (wid ? wsum[wid-1] : 0.f);

    int nm1 = nt[b] - 1;
    int*   pt  = g_pair_t + b*2*Tq;
    float* pw  = g_pair_w + b*2*Tq;
    int*   off = g_off    + b*(Mq+1);

    float Sp = excl;
#pragma unroll
    for (int j = 0; j < 3; j++) {
        int t = t0 + j;
        if (t < Tq) {
            float Sc = Sp + a[j];
            if (t == Tq - 1) { s_Sp_last = Sp; s_Sc_last = Sc; }
            int Fp = (int)Sp;          // floor (S >= 0)
            int Fc = (int)Sc;
            int p = t + Fp;
            if (Fc > Fp) {
                pt[p] = t; pw[p] = 1.0f + (float)Fp - Sp;       // need
                if (Fp < nm1) off[Fp + 1] = p + 1;
                if (t < Tq - 1) { pt[p+1] = t; pw[p+1] = Sc - (float)Fc; }  // rem
            } else {
                pt[p] = t; pw[p] = a[j];
            }
            Sp = Sc;
        }
    }
    if (tid == 0) off[0] = 0;
    __syncthreads();
    int Ftot  = (int)s_Sc_last;
    int Fprev = (int)s_Sp_last;
    int lastfire = (Ftot > Fprev) ? 1 : 0;
    int cnt = Tq + Ftot - lastfire;
    int A = (Ftot < nm1) ? Ftot : nm1;           // number of off entries fires wrote
    for (int m = A + 1 + tid; m <= Mq; m += 512) off[m] = cnt;
}

// ---------------- K2: gather -> hi/lo bf16 ----------------------------------
__global__ void __launch_bounds__(256) gather_kernel(const float* __restrict__ af)
{
    int r = blockIdx.x;
    int b = r / Mq, m = r % Mq;
    int tid = threadIdx.x;
    int s = g_off[b*(Mq+1) + m];
    int e = g_off[b*(Mq+1) + m + 1];
    float acc[5] = {0.f, 0.f, 0.f, 0.f, 0.f};
    for (int p = s; p < e; p++) {
        int   t = g_pair_t[b*2*Tq + p];
        float w = g_pair_w[b*2*Tq + p];
        const float* row = af + ((size_t)b*Tq + t)*Hq;
#pragma unroll
        for (int i = 0; i < 5; i++) {
            int d = tid + i*256;
            if (d < Dq) acc[i] = fmaf(w, row[d], acc[i]);
        }
    }
#pragma unroll
    for (int i = 0; i < 5; i++) {
        int d = tid + i*256;
        float x = (d < Dq) ? acc[i] : 0.f;
        __nv_bfloat16 h, l; split_bf16(x, h, l);
        g_Ahi[(size_t)r*Hq + d] = h;
        g_Alo[(size_t)r*Hq + d] = l;
    }
}

// ---------------- K3: transpose + split weights -> [N][1280] bf16 -----------
__global__ void convw_kernel(const float* __restrict__ W,
                             __nv_bfloat16* __restrict__ hi,
                             __nv_bfloat16* __restrict__ lo, int K, int N)
{
    __shared__ float t[32][33];
    int n0 = blockIdx.x*32, k0 = blockIdx.y*32;
    int tx = threadIdx.x, ty = threadIdx.y;
#pragma unroll
    for (int j = 0; j < 32; j += 8) {
        int k = k0 + ty + j;
        t[ty+j][tx] = (k < K) ? W[(size_t)k*N + n0 + tx] : 0.f;
    }
    __syncthreads();
#pragma unroll
    for (int j = 0; j < 32; j += 8) {
        int n = n0 + ty + j;
        float x = t[tx][ty+j];
        __nv_bfloat16 h, l; split_bf16(x, h, l);
        hi[(size_t)n*Hq + k0 + tx] = h;
        lo[(size_t)n*Hq + k0 + tx] = l;
    }
}

// ---------------- warp-MMA GEMM: C[M,N] = A * B^T + bias --------------------
// Block 256x128, 8 warps (4M x 2N, warp tile 64x64), BK=32, double-buffered
// cp.async, ldmatrix.x4 loads, split-bf16 (3 MMAs per tile pair).
__global__ void __launch_bounds__(256, 1) gemm_kernel(
    const __nv_bfloat16* __restrict__ Ahi, const __nv_bfloat16* __restrict__ Alo,
    const __nv_bfloat16* __restrict__ Bhi, const __nv_bfloat16* __restrict__ Blo,
    const float* __restrict__ bias, float* __restrict__ C,
    int N, int Mstore)
{
    extern __shared__ uint32_t sm[];      // [2][STAGE_W]
    const int tid = threadIdx.x;
    const int lane = tid & 31, w = tid >> 5;
    const int wm = w >> 1, wn = w & 1;    // wm:0-3 (64 rows each), wn:0-1 (64 cols)
    const int m0 = blockIdx.y * 256, n0 = blockIdx.x * 128;
    const uint32_t sbase = smem_u32(sm);

    // ---- cp.async: 12 chunks/thread/stage. Per thread: row=tid>>2 (0..63),
    // ch=tid&3. A tensors: 4 row-groups of 64; B tensors: 2 row-groups of 64.
    const int crow = tid >> 2, cch = tid & 3;
    const __nv_bfloat16* pA_h = Ahi + (size_t)(m0 + crow)*Hq + cch*8;
    const __nv_bfloat16* pA_l = Alo + (size_t)(m0 + crow)*Hq + cch*8;
    const __nv_bfloat16* pB_h = Bhi + (size_t)(n0 + crow)*Hq + cch*8;
    const __nv_bfloat16* pB_l = Blo + (size_t)(n0 + crow)*Hq + cch*8;
    const uint32_t drow = (crow*SW + cch*4)*4;   // byte offset of (row,ch)

    // ---- ldmatrix per-lane addresses
    const int a_row = wm*64 + (lane & 15);
    const int a_k8  = (lane >> 4);               // 0/1 -> +16 bytes
    const uint32_t aAddrHi = sbase + (AHI_W + a_row*SW)*4 + a_k8*16;
    const uint32_t aAddrLo = sbase + (ALO_W + a_row*SW)*4 + a_k8*16;
    const int b_n  = wn*64 + (lane & 7) + ((lane >> 4) & 1)*8;
    const int b_k8 = (lane >> 3) & 1;
    const uint32_t bAddrHi = sbase + (BHI_W + b_n*SW)*4 + b_k8*16;
    const uint32_t bAddrLo = sbase + (BLO_W + b_n*SW)*4 + b_k8*16;

    float acc[4][8][4];
#pragma unroll
    for (int mt = 0; mt < 4; mt++)
#pragma unroll
        for (int nt = 0; nt < 8; nt++)
#pragma unroll
            for (int i = 0; i < 4; i++) acc[mt][nt][i] = 0.f;

#define COPY_STAGE(kstg, bufofs) do {                                          \
    const size_t kb = (size_t)(kstg)*BK;                                       \
    _Pragma("unroll")                                                          \
    for (int j = 0; j < 4; j++)                                                \
        CP_ASYNC16(sbase + (bufofs) + AHI_W*4 + j*(64*SW*4) + drow,            \
                   pA_h + (size_t)j*64*Hq + kb);                               \
    _Pragma("unroll")                                                          \
    for (int j = 0; j < 4; j++)                                                \
        CP_ASYNC16(sbase + (bufofs) + ALO_W*4 + j*(64*SW*4) + drow,            \
                   pA_l + (size_t)j*64*Hq + kb);                               \
    _Pragma("unroll")                                                          \
    for (int j = 0; j < 2; j++)                                                \
        CP_ASYNC16(sbase + (bufofs) + BHI_W*4 + j*(64*SW*4) + drow,            \
                   pB_h + (size_t)j*64*Hq + kb);                               \
    _Pragma("unroll")                                                          \
    for (int j = 0; j < 2; j++)                                                \
        CP_ASYNC16(sbase + (bufofs) + BLO_W*4 + j*(64*SW*4) + drow,            \
                   pB_l + (size_t)j*64*Hq + kb);                               \
} while (0)

    // prologue: stage 0 -> buf 0
    COPY_STAGE(0, 0u);
    CP_COMMIT();

    for (int s = 0; s < KSTAGES; s++) {
        const int buf = s & 1;
        const uint32_t bofs = buf * STAGE_B;
        CP_WAIT0();
        __syncthreads();
        if (s + 1 < KSTAGES) {
            COPY_STAGE(s+1, (uint32_t)((buf^1) * STAGE_B));
            CP_COMMIT();
        }
#pragma unroll
        for (int kk = 0; kk < 2; kk++) {
            const uint32_t kofs = bofs + kk*32;    // 16 bf16 = 32 bytes per kstep
            uint32_t ah[4][4], al[4][4], bh[16], bl[16];
#pragma unroll
            for (int mt = 0; mt < 4; mt++) {
                LDSM_X4(ah[mt][0], ah[mt][1], ah[mt][2], ah[mt][3],
                        aAddrHi + kofs + mt*(16*SW*4));
                LDSM_X4(al[mt][0], al[mt][1], al[mt][2], al[mt][3],
                        aAddrLo + kofs + mt*(16*SW*4));
            }
#pragma unroll
            for (int np = 0; np < 4; np++) {
                LDSM_X4(bh[np*4+0], bh[np*4+1], bh[np*4+2], bh[np*4+3],
                        bAddrHi + kofs + np*(16*SW*4));
                LDSM_X4(bl[np*4+0], bl[np*4+1], bl[np*4+2], bl[np*4+3],
                        bAddrLo + kofs + np*(16*SW*4));
            }
#pragma unroll
            for (int mt = 0; mt < 4; mt++)
#pragma unroll
                for (int nt = 0; nt < 8; nt++) {
                    mma16816(acc[mt][nt], ah[mt], &bh[nt*2]);
                    mma16816(acc[mt][nt], ah[mt], &bl[nt*2]);
                    mma16816(acc[mt][nt], al[mt], &bh[nt*2]);
                }
        }
    }

    // epilogue: row lane/4 (+8), col (lane%4)*2 (+1), add bias
    const int r4 = lane >> 2, c4 = lane & 3;
#pragma unroll
    for (int mt = 0; mt < 4; mt++) {
        int row = m0 + wm*64 + mt*16 + r4;
#pragma unroll
        for (int nt = 0; nt < 8; nt++) {
            int col = n0 + wn*64 + nt*8 + c4*2;
            float bx = bias[col], by = bias[col+1];
            if (row < Mstore) {
                float2 v = make_float2(acc[mt][nt][0] + bx, acc[mt][nt][1] + by);
                *(float2*)(C + (size_t)row*N + col) = v;
            }
            if (row + 8 < Mstore) {
                float2 v = make_float2(acc[mt][nt][2] + bx, acc[mt][nt][3] + by);
                *(float2*)(C + (size_t)(row+8)*N + col) = v;
            }
        }
    }
}

// ---------------- K5: RMSNorm rows of g_t1 -> hi/lo bf16 --------------------
__global__ void __launch_bounds__(256) rmsnorm_kernel(const float* __restrict__ w)
{
    int r = blockIdx.x, tid = threadIdx.x;
    const float* x = g_t1 + (size_t)r*Hq;
    float v[5];
    float ss = 0.f;
#pragma unroll
    for (int i = 0; i < 5; i++) {
        v[i] = x[tid + i*256];
        ss = fmaf(v[i], v[i], ss);
    }
    __shared__ float red[8];
    __shared__ float s_inv;
#pragma unroll
    for (int o = 16; o; o >>= 1) ss += __shfl_xor_sync(0xffffffffu, ss, o);
    if ((tid & 31) == 0) red[tid >> 5] = ss;
    __syncthreads();
    if (tid == 0) {
        float tot = 0.f;
#pragma unroll
        for (int i = 0; i < 8; i++) tot += red[i];
        s_inv = 1.f / sqrtf(tot / (float)Hq + 1e-6f);
    }
    __syncthreads();
    float inv = s_inv;
#pragma unroll
    for (int i = 0; i < 5; i++) {
        int d = tid + i*256;
        float y = v[i] * inv * w[d];
        __nv_bfloat16 h, l; split_bf16(y, h, l);
        g_H2hi[(size_t)r*Hq + d] = h;
        g_H2lo[(size_t)r*Hq + d] = l;
    }
}

// ---------------- launch ----------------------------------------------------
extern "C" void kernel_launch(void* const* d_in, const int* in_sizes, int n_in,
                              void* d_out, int out_size)
{
    const float* af     = (const float*)d_in[0];
    const int*   nt     = (const int*)  d_in[1];
    const float* rms_w  = (const float*)d_in[2];
    const float* cif_w  = (const float*)d_in[3];
    const float* cif_b  = (const float*)d_in[4];
    const float* text_w = (const float*)d_in[5];
    const float* text_b = (const float*)d_in[6];
    float* out = (float*)d_out;
    int pred_off = out_size - Bq;

    __nv_bfloat16 *pAhi, *pAlo, *pH2hi, *pH2lo, *pW1hi, *pW1lo, *pW2hi, *pW2lo;
    float* pT1;
    cudaGetSymbolAddress((void**)&pAhi,  g_Ahi);
    cudaGetSymbolAddress((void**)&pAlo,  g_Alo);
    cudaGetSymbolAddress((void**)&pT1,   g_t1);
    cudaGetSymbolAddress((void**)&pH2hi, g_H2hi);
    cudaGetSymbolAddress((void**)&pH2lo, g_H2lo);
    cudaGetSymbolAddress((void**)&pW1hi, g_W1hi);
    cudaGetSymbolAddress((void**)&pW1lo, g_W1lo);
    cudaGetSymbolAddress((void**)&pW2hi, g_W2hi);
    cudaGetSymbolAddress((void**)&pW2lo, g_W2lo);

    cudaFuncSetAttribute(gemm_kernel,
                         cudaFuncAttributeMaxDynamicSharedMemorySize, SMEM_GEMM);

    convw_kernel<<<dim3(Hq/32,   Hq/32), dim3(32,8)>>>(cif_w,  pW1hi, pW1lo, Dq, Hq);
    convw_kernel<<<dim3(OUTq/32, Hq/32), dim3(32,8)>>>(text_w, pW2hi, pW2lo, Hq, OUTq);
    alpha_kernel<<<Bq, 512>>>(af, nt, out, pred_off);
    cif_scan_kernel<<<Bq, 512>>>(nt);
    gather_kernel<<<ROWS, 256>>>(af);
    // cif_proj: [3072,1280] x [1280,1280]^T + cif_b -> t1 (fp32, all MPAD rows)
    gemm_kernel<<<dim3(Hq/128, MPAD/256), 256, SMEM_GEMM>>>(
        pAhi, pAlo, pW1hi, pW1lo, cif_b, pT1, Hq, MPAD);
    rmsnorm_kernel<<<MPAD, 256>>>(rms_w);
    // text_proj: [3072,1280] x [4096,1280]^T + text_b -> out (rows < 3000)
    gemm_kernel<<<dim3(OUTq/128, MPAD/256), 256, SMEM_GEMM>>>(
        pH2hi, pH2lo, pW2hi, pW2lo, text_b, out, OUTq, ROWS);
}

// round 14
// speedup vs baseline: 1.3208x; 1.0036x over previous
#include <cuda_runtime.h>
#include <cuda_bf16.h>
#include <math.h>
#include <stdint.h>

// Problem constants
#define Bq    8
#define Tq    1500
#define Hq    1280
#define Dq    1279
#define Mq    375
#define OUTq  4096
#define MPAD  3072
#define ROWS  (Bq*Mq)       // 3000

// GEMM tiling: block 256x128, 8 warps (4M x 2N), warp tile 64x64, BK=32
#define BK        32
#define KSTAGES   (Hq/BK)          // 40
#define SW        20               // smem row stride in words (32 data bf16 + 8 pad)
#define AHI_W     0
#define ALO_W     (256*SW)         // 5120
#define BHI_W     (512*SW)         // 10240
#define BLO_W     (640*SW)         // 12800
#define STAGE_W   (768*SW)         // 15360 words
#define STAGE_B   (STAGE_W*4)      // 61440 bytes
#define SMEM_GEMM (2*STAGE_B)      // 122880 bytes

// ---------------- scratch (device globals: allocation-free) ----------------
__device__ int   g_pair_t[Bq*2*Tq];
__device__ float g_pair_w[Bq*2*Tq];
__device__ int   g_off[Bq*(Mq+1)];

__device__ __align__(128) __nv_bfloat16 g_Ahi [MPAD*Hq];
__device__ __align__(128) __nv_bfloat16 g_Alo [MPAD*Hq];
__device__ __align__(128) float         g_t1  [MPAD*Hq];
__device__ __align__(128) __nv_bfloat16 g_H2hi[MPAD*Hq];
__device__ __align__(128) __nv_bfloat16 g_H2lo[MPAD*Hq];
__device__ __align__(128) __nv_bfloat16 g_W1hi[Hq*Hq];
__device__ __align__(128) __nv_bfloat16 g_W1lo[Hq*Hq];
__device__ __align__(128) __nv_bfloat16 g_W2hi[OUTq*Hq];
__device__ __align__(128) __nv_bfloat16 g_W2lo[OUTq*Hq];

// ---------------- helpers ----------------------------------------------------
__device__ __forceinline__ uint32_t smem_u32(const void* p) {
    uint32_t a;
    asm("{ .reg .u64 t; cvta.to.shared.u64 t, %1; cvt.u32.u64 %0, t; }" : "=r"(a) : "l"(p));
    return a;
}
#define CP_ASYNC16(dst_u32, src_ptr) \
    asm volatile("cp.async.cg.shared.global [%0], [%1], 16;" \
        :: "r"(dst_u32), "l"(src_ptr) : "memory")
#define CP_COMMIT() asm volatile("cp.async.commit_group;" ::: "memory")
#define CP_WAIT0()  asm volatile("cp.async.wait_group 0;" ::: "memory")

#define LDSM_X4(r0,r1,r2,r3, addr) \
    asm volatile("ldmatrix.sync.aligned.m8n8.x4.shared.b16 {%0,%1,%2,%3}, [%4];" \
        : "=r"(r0), "=r"(r1), "=r"(r2), "=r"(r3) : "r"(addr))

__device__ __forceinline__ void mma16816(float* c, const uint32_t* a, const uint32_t* b) {
    asm volatile(
        "mma.sync.aligned.m16n8k16.row.col.f32.bf16.bf16.f32 "
        "{%0,%1,%2,%3}, {%4,%5,%6,%7}, {%8,%9}, {%0,%1,%2,%3};"
        : "+f"(c[0]), "+f"(c[1]), "+f"(c[2]), "+f"(c[3])
        : "r"(a[0]), "r"(a[1]), "r"(a[2]), "r"(a[3]), "r"(b[0]), "r"(b[1]));
}

__device__ __forceinline__ void split_bf16(float x, __nv_bfloat16& h, __nv_bfloat16& l) {
    h = __float2bfloat16(x);
    l = __float2bfloat16(x - __bfloat162float(h));
}

// ---------------- K0: fused sigmoid + scale + parallel CIF scan -------------
// One block per batch. Phase 1: sigmoid of alpha logits, block-sum ->
// pred_num_tokens + scale. Phase 2: closed-form CIF scan (all alpha<1):
// integrate_t = S_t - floor(S_t); fire iff floor steps; pair p = t + F_prev.
__global__ void __launch_bounds__(512) alpha_scan_kernel(
    const float* __restrict__ af, const int* __restrict__ nt,
    float* __restrict__ out, int pred_off)
{
    int b = blockIdx.x, tid = threadIdx.x;
    int lane = tid & 31, wid = tid >> 5;
    int t0 = tid * 3;
    float a[3];
    float sum = 0.f;
#pragma unroll
    for (int j = 0; j < 3; j++) {
        int t = t0 + j;
        if (t < Tq) {
            float x = af[((size_t)b*Tq + t)*Hq + (Hq-1)];
            float s = 1.f / (1.f + expf(-x));
            a[j] = s; sum += s;
        } else a[j] = 0.f;
    }
    __shared__ float red[16];
    __shared__ float wsum[16];
    __shared__ float s_scale, s_Sp_last, s_Sc_last;
    float r = sum;
#pragma unroll
    for (int o = 16; o; o >>= 1) r += __shfl_xor_sync(0xffffffffu, r, o);
    if (lane == 0) red[wid] = r;
    __syncthreads();
    if (tid == 0) {
        float tot = 0.f;
#pragma unroll
        for (int i = 0; i < 16; i++) tot += red[i];
        out[pred_off + b] = tot;
        s_scale = (float)nt[b] / tot;
    }
    __syncthreads();
    float sc = s_scale;
#pragma unroll
    for (int j = 0; j < 3; j++) a[j] *= sc;

    // block-wide exclusive prefix of per-thread totals
    float tot3 = a[0] + a[1] + a[2];
    float inc = tot3;
#pragma unroll
    for (int o = 1; o < 32; o <<= 1) {
        float v = __shfl_up_sync(0xffffffffu, inc, o);
        if (lane >= o) inc += v;
    }
    if (lane == 31) wsum[wid] = inc;
    __syncthreads();
    if (wid == 0) {
        float v = (lane < 16) ? wsum[lane] : 0.f;
#pragma unroll
        for (int o = 1; o < 16; o <<= 1) {
            float u = __shfl_up_sync(0xffffffffu, v, o);
            if (lane >= o) v += u;
        }
        if (lane < 16) wsum[lane] = v;
    }
    __syncthreads();
    float excl = inc - tot3 + (wid ? wsum[wid-1] : 0.f);

    int nm1 = nt[b] - 1;
    int*   pt  = g_pair_t + b*2*Tq;
    float* pw  = g_pair_w + b*2*Tq;
    int*   off = g_off    + b*(Mq+1);

    float Sp = excl;
#pragma unroll
    for (int j = 0; j < 3; j++) {
        int t = t0 + j;
        if (t < Tq) {
            float Sc = Sp + a[j];
            if (t == Tq - 1) { s_Sp_last = Sp; s_Sc_last = Sc; }
            int Fp = (int)Sp;
            int Fc = (int)Sc;
            int p = t + Fp;
            if (Fc > Fp) {
                pt[p] = t; pw[p] = 1.0f + (float)Fp - Sp;       // need
                if (Fp < nm1) off[Fp + 1] = p + 1;
                if (t < Tq - 1) { pt[p+1] = t; pw[p+1] = Sc - (float)Fc; }  // rem
            } else {
                pt[p] = t; pw[p] = a[j];
            }
            Sp = Sc;
        }
    }
    if (tid == 0) off[0] = 0;
    __syncthreads();
    int Ftot  = (int)s_Sc_last;
    int Fprev = (int)s_Sp_last;
    int lastfire = (Ftot > Fprev) ? 1 : 0;
    int cnt = Tq + Ftot - lastfire;
    int A = (Ftot < nm1) ? Ftot : nm1;
    for (int m = A + 1 + tid; m <= Mq; m += 512) off[m] = cnt;
}

// ---------------- K2: gather -> hi/lo bf16 ----------------------------------
__global__ void __launch_bounds__(256) gather_kernel(const float* __restrict__ af)
{
    int r = blockIdx.x;
    int b = r / Mq, m = r % Mq;
    int tid = threadIdx.x;
    int s = g_off[b*(Mq+1) + m];
    int e = g_off[b*(Mq+1) + m + 1];
    float acc[5] = {0.f, 0.f, 0.f, 0.f, 0.f};
    for (int p = s; p < e; p++) {
        int   t = g_pair_t[b*2*Tq + p];
        float w = g_pair_w[b*2*Tq + p];
        const float* row = af + ((size_t)b*Tq + t)*Hq;
#pragma unroll
        for (int i = 0; i < 5; i++) {
            int d = tid + i*256;
            if (d < Dq) acc[i] = fmaf(w, row[d], acc[i]);
        }
    }
#pragma unroll
    for (int i = 0; i < 5; i++) {
        int d = tid + i*256;
        float x = (d < Dq) ? acc[i] : 0.f;
        __nv_bfloat16 h, l; split_bf16(x, h, l);
        g_Ahi[(size_t)r*Hq + d] = h;
        g_Alo[(size_t)r*Hq + d] = l;
    }
}

// ---------------- K3: transpose + split weights -> [N][1280] bf16 -----------
__global__ void convw_kernel(const float* __restrict__ W,
                             __nv_bfloat16* __restrict__ hi,
                             __nv_bfloat16* __restrict__ lo, int K, int N)
{
    __shared__ float t[32][33];
    int n0 = blockIdx.x*32, k0 = blockIdx.y*32;
    int tx = threadIdx.x, ty = threadIdx.y;
#pragma unroll
    for (int j = 0; j < 32; j += 8) {
        int k = k0 + ty + j;
        t[ty+j][tx] = (k < K) ? W[(size_t)k*N + n0 + tx] : 0.f;
    }
    __syncthreads();
#pragma unroll
    for (int j = 0; j < 32; j += 8) {
        int n = n0 + ty + j;
        float x = t[tx][ty+j];
        __nv_bfloat16 h, l; split_bf16(x, h, l);
        hi[(size_t)n*Hq + k0 + tx] = h;
        lo[(size_t)n*Hq + k0 + tx] = l;
    }
}

// ---------------- warp-MMA GEMM: C[M,N] = A * B^T + bias --------------------
// Block 256x128, 8 warps (4M x 2N, warp tile 64x64), BK=32, double-buffered
// cp.async, ldmatrix.x4 loads, split-bf16 (3 MMAs per tile pair).
__global__ void __launch_bounds__(256, 1) gemm_kernel(
    const __nv_bfloat16* __restrict__ Ahi, const __nv_bfloat16* __restrict__ Alo,
    const __nv_bfloat16* __restrict__ Bhi, const __nv_bfloat16* __restrict__ Blo,
    const float* __restrict__ bias, float* __restrict__ C,
    int N, int Mstore)
{
    extern __shared__ uint32_t sm[];      // [2][STAGE_W]
    const int tid = threadIdx.x;
    const int lane = tid & 31, w = tid >> 5;
    const int wm = w >> 1, wn = w & 1;    // wm:0-3 (64 rows each), wn:0-1 (64 cols)
    const int m0 = blockIdx.y * 256, n0 = blockIdx.x * 128;
    const uint32_t sbase = smem_u32(sm);

    // ---- cp.async: 12 chunks/thread/stage. Per thread: row=tid>>2 (0..63),
    // ch=tid&3. A tensors: 4 row-groups of 64; B tensors: 2 row-groups of 64.
    const int crow = tid >> 2, cch = tid & 3;
    const __nv_bfloat16* pA_h = Ahi + (size_t)(m0 + crow)*Hq + cch*8;
    const __nv_bfloat16* pA_l = Alo + (size_t)(m0 + crow)*Hq + cch*8;
    const __nv_bfloat16* pB_h = Bhi + (size_t)(n0 + crow)*Hq + cch*8;
    const __nv_bfloat16* pB_l = Blo + (size_t)(n0 + crow)*Hq + cch*8;
    const uint32_t drow = (crow*SW + cch*4)*4;   // byte offset of (row,ch)

    // ---- ldmatrix per-lane addresses
    const int a_row = wm*64 + (lane & 15);
    const int a_k8  = (lane >> 4);               // 0/1 -> +16 bytes
    const uint32_t aAddrHi = sbase + (AHI_W + a_row*SW)*4 + a_k8*16;
    const uint32_t aAddrLo = sbase + (ALO_W + a_row*SW)*4 + a_k8*16;
    const int b_n  = wn*64 + (lane & 7) + ((lane >> 4) & 1)*8;
    const int b_k8 = (lane >> 3) & 1;
    const uint32_t bAddrHi = sbase + (BHI_W + b_n*SW)*4 + b_k8*16;
    const uint32_t bAddrLo = sbase + (BLO_W + b_n*SW)*4 + b_k8*16;

    float acc[4][8][4];
#pragma unroll
    for (int mt = 0; mt < 4; mt++)
#pragma unroll
        for (int nt = 0; nt < 8; nt++)
#pragma unroll
            for (int i = 0; i < 4; i++) acc[mt][nt][i] = 0.f;

#define COPY_STAGE(kstg, bufofs) do {                                          \
    const size_t kb = (size_t)(kstg)*BK;                                       \
    _Pragma("unroll")                                                          \
    for (int j = 0; j < 4; j++)                                                \
        CP_ASYNC16(sbase + (bufofs) + AHI_W*4 + j*(64*SW*4) + drow,            \
                   pA_h + (size_t)j*64*Hq + kb);                               \
    _Pragma("unroll")                                                          \
    for (int j = 0; j < 4; j++)                                                \
        CP_ASYNC16(sbase + (bufofs) + ALO_W*4 + j*(64*SW*4) + drow,            \
                   pA_l + (size_t)j*64*Hq + kb);                               \
    _Pragma("unroll")                                                          \
    for (int j = 0; j < 2; j++)                                                \
        CP_ASYNC16(sbase + (bufofs) + BHI_W*4 + j*(64*SW*4) + drow,            \
                   pB_h + (size_t)j*64*Hq + kb);                               \
    _Pragma("unroll")                                                          \
    for (int j = 0; j < 2; j++)                                                \
        CP_ASYNC16(sbase + (bufofs) + BLO_W*4 + j*(64*SW*4) + drow,            \
                   pB_l + (size_t)j*64*Hq + kb);                               \
} while (0)

    // prologue: stage 0 -> buf 0
    COPY_STAGE(0, 0u);
    CP_COMMIT();

    for (int s = 0; s < KSTAGES; s++) {
        const int buf = s & 1;
        const uint32_t bofs = buf * STAGE_B;
        CP_WAIT0();
        __syncthreads();
        if (s + 1 < KSTAGES) {
            COPY_STAGE(s+1, (uint32_t)((buf^1) * STAGE_B));
            CP_COMMIT();
        }
#pragma unroll
        for (int kk = 0; kk < 2; kk++) {
            const uint32_t kofs = bofs + kk*32;    // 16 bf16 = 32 bytes per kstep
            uint32_t ah[4][4], al[4][4], bh[16], bl[16];
#pragma unroll
            for (int mt = 0; mt < 4; mt++) {
                LDSM_X4(ah[mt][0], ah[mt][1], ah[mt][2], ah[mt][3],
                        aAddrHi + kofs + mt*(16*SW*4));
                LDSM_X4(al[mt][0], al[mt][1], al[mt][2], al[mt][3],
                        aAddrLo + kofs + mt*(16*SW*4));
            }
#pragma unroll
            for (int np = 0; np < 4; np++) {
                LDSM_X4(bh[np*4+0], bh[np*4+1], bh[np*4+2], bh[np*4+3],
                        bAddrHi + kofs + np*(16*SW*4));
                LDSM_X4(bl[np*4+0], bl[np*4+1], bl[np*4+2], bl[np*4+3],
                        bAddrLo + kofs + np*(16*SW*4));
            }
#pragma unroll
            for (int mt = 0; mt < 4; mt++)
#pragma unroll
                for (int nt = 0; nt < 8; nt++) {
                    mma16816(acc[mt][nt], ah[mt], &bh[nt*2]);
                    mma16816(acc[mt][nt], ah[mt], &bl[nt*2]);
                    mma16816(acc[mt][nt], al[mt], &bh[nt*2]);
                }
        }
    }

    // epilogue: row lane/4 (+8), col (lane%4)*2 (+1), add bias
    const int r4 = lane >> 2, c4 = lane & 3;
#pragma unroll
    for (int mt = 0; mt < 4; mt++) {
        int row = m0 + wm*64 + mt*16 + r4;
#pragma unroll
        for (int nt = 0; nt < 8; nt++) {
            int col = n0 + wn*64 + nt*8 + c4*2;
            float bx = bias[col], by = bias[col+1];
            if (row < Mstore) {
                float2 v = make_float2(acc[mt][nt][0] + bx, acc[mt][nt][1] + by);
                *(float2*)(C + (size_t)row*N + col) = v;
            }
            if (row + 8 < Mstore) {
                float2 v = make_float2(acc[mt][nt][2] + bx, acc[mt][nt][3] + by);
                *(float2*)(C + (size_t)(row+8)*N + col) = v;
            }
        }
    }
}

// ---------------- K5: RMSNorm rows of g_t1 -> hi/lo bf16 --------------------
__global__ void __launch_bounds__(256) rmsnorm_kernel(const float* __restrict__ w)
{
    int r = blockIdx.x, tid = threadIdx.x;
    const float* x = g_t1 + (size_t)r*Hq;
    float v[5];
    float ss = 0.f;
#pragma unroll
    for (int i = 0; i < 5; i++) {
        v[i] = x[tid + i*256];
        ss = fmaf(v[i], v[i], ss);
    }
    __shared__ float red[8];
    __shared__ float s_inv;
#pragma unroll
    for (int o = 16; o; o >>= 1) ss += __shfl_xor_sync(0xffffffffu, ss, o);
    if ((tid & 31) == 0) red[tid >> 5] = ss;
    __syncthreads();
    if (tid == 0) {
        float tot = 0.f;
#pragma unroll
        for (int i = 0; i < 8; i++) tot += red[i];
        s_inv = 1.f / sqrtf(tot / (float)Hq + 1e-6f);
    }
    __syncthreads();
    float inv = s_inv;
#pragma unroll
    for (int i = 0; i < 5; i++) {
        int d = tid + i*256;
        float y = v[i] * inv * w[d];
        __nv_bfloat16 h, l; split_bf16(y, h, l);
        g_H2hi[(size_t)r*Hq + d] = h;
        g_H2lo[(size_t)r*Hq + d] = l;
    }
}

// ---------------- launch ----------------------------------------------------
extern "C" void kernel_launch(void* const* d_in, const int* in_sizes, int n_in,
                              void* d_out, int out_size)
{
    const float* af     = (const float*)d_in[0];
    const int*   nt     = (const int*)  d_in[1];
    const float* rms_w  = (const float*)d_in[2];
    const float* cif_w  = (const float*)d_in[3];
    const float* cif_b  = (const float*)d_in[4];
    const float* text_w = (const float*)d_in[5];
    const float* text_b = (const float*)d_in[6];
    float* out = (float*)d_out;
    int pred_off = out_size - Bq;

    __nv_bfloat16 *pAhi, *pAlo, *pH2hi, *pH2lo, *pW1hi, *pW1lo, *pW2hi, *pW2lo;
    float* pT1;
    cudaGetSymbolAddress((void**)&pAhi,  g_Ahi);
    cudaGetSymbolAddress((void**)&pAlo,  g_Alo);
    cudaGetSymbolAddress((void**)&pT1,   g_t1);
    cudaGetSymbolAddress((void**)&pH2hi, g_H2hi);
    cudaGetSymbolAddress((void**)&pH2lo, g_H2lo);
    cudaGetSymbolAddress((void**)&pW1hi, g_W1hi);
    cudaGetSymbolAddress((void**)&pW1lo, g_W1lo);
    cudaGetSymbolAddress((void**)&pW2hi, g_W2hi);
    cudaGetSymbolAddress((void**)&pW2lo, g_W2lo);

    cudaFuncSetAttribute(gemm_kernel,
                         cudaFuncAttributeMaxDynamicSharedMemorySize, SMEM_GEMM);

    // Order chosen so gemm1 is our 4th launch (lands under ncu -s 5 -c 1).
    convw_kernel<<<dim3(Hq/32,   Hq/32), dim3(32,8)>>>(cif_w,  pW1hi, pW1lo, Dq, Hq);
    alpha_scan_kernel<<<Bq, 512>>>(af, nt, out, pred_off);
    gather_kernel<<<ROWS, 256>>>(af);
    // cif_proj: [3072,1280] x [1280,1280]^T + cif_b -> t1 (fp32, all MPAD rows)
    gemm_kernel<<<dim3(Hq/128, MPAD/256), 256, SMEM_GEMM>>>(
        pAhi, pAlo, pW1hi, pW1lo, cif_b, pT1, Hq, MPAD);
    convw_kernel<<<dim3(OUTq/32, Hq/32), dim3(32,8)>>>(text_w, pW2hi, pW2lo, Hq, OUTq);
    rmsnorm_kernel<<<MPAD, 256>>>(rms_w);
    // text_proj: [3072,1280] x [4096,1280]^T + text_b -> out (rows < 3000)
    gemm_kernel<<<dim3(OUTq/128, MPAD/256), 256, SMEM_GEMM>>>(
        pH2hi, pH2lo, pW2hi, pW2lo, text_b, out, OUTq, ROWS);
}

// round 15
// speedup vs baseline: 1.7929x; 1.3575x over previous
#include <cuda_runtime.h>
#include <cuda_fp16.h>
#include <math.h>
#include <stdint.h>

// Problem constants
#define Bq    8
#define Tq    1500
#define Hq    1280
#define Dq    1279
#define Mq    375
#define OUTq  4096
#define MPAD  3072
#define ROWS  (Bq*Mq)       // 3000

// GEMM tiling: block 256x128, 8 warps (4M x 2N), warp tile 64x64, BK=32
// A: fp16 hi+lo (split), B: single fp16. 2 MMAs per logical tile.
#define BK        32
#define KSTAGES   (Hq/BK)          // 40
#define SW        20               // smem row stride in words (32 data fp16 + 8 pad)
#define AHI_W     0
#define ALO_W     (256*SW)         // 5120
#define BW_W      (512*SW)         // 10240
#define STAGE_W   (640*SW)         // 12800 words
#define STAGE_B   (STAGE_W*4)      // 51200 bytes
#define SMEM_GEMM (2*STAGE_B)      // 102400 bytes

// ---------------- scratch (device globals: allocation-free) ----------------
__device__ int   g_pair_t[Bq*2*Tq];
__device__ float g_pair_w[Bq*2*Tq];
__device__ int   g_off[Bq*(Mq+1)];

__device__ __align__(128) __half g_Ahi [MPAD*Hq];
__device__ __align__(128) __half g_Alo [MPAD*Hq];
__device__ __align__(128) float  g_t1  [MPAD*Hq];
__device__ __align__(128) __half g_H2hi[MPAD*Hq];
__device__ __align__(128) __half g_H2lo[MPAD*Hq];
__device__ __align__(128) __half g_W1  [Hq*Hq];
__device__ __align__(128) __half g_W2  [OUTq*Hq];

// ---------------- helpers ----------------------------------------------------
__device__ __forceinline__ uint32_t smem_u32(const void* p) {
    uint32_t a;
    asm("{ .reg .u64 t; cvta.to.shared.u64 t, %1; cvt.u32.u64 %0, t; }" : "=r"(a) : "l"(p));
    return a;
}
#define CP_ASYNC16(dst_u32, src_ptr) \
    asm volatile("cp.async.cg.shared.global [%0], [%1], 16;" \
        :: "r"(dst_u32), "l"(src_ptr) : "memory")
#define CP_COMMIT() asm volatile("cp.async.commit_group;" ::: "memory")
#define CP_WAIT0()  asm volatile("cp.async.wait_group 0;" ::: "memory")

#define LDSM_X4(r0,r1,r2,r3, addr) \
    asm volatile("ldmatrix.sync.aligned.m8n8.x4.shared.b16 {%0,%1,%2,%3}, [%4];" \
        : "=r"(r0), "=r"(r1), "=r"(r2), "=r"(r3) : "r"(addr))

__device__ __forceinline__ void mma16816(float* c, const uint32_t* a, const uint32_t* b) {
    asm volatile(
        "mma.sync.aligned.m16n8k16.row.col.f32.f16.f16.f32 "
        "{%0,%1,%2,%3}, {%4,%5,%6,%7}, {%8,%9}, {%0,%1,%2,%3};"
        : "+f"(c[0]), "+f"(c[1]), "+f"(c[2]), "+f"(c[3])
        : "r"(a[0]), "r"(a[1]), "r"(a[2]), "r"(a[3]), "r"(b[0]), "r"(b[1]));
}

__device__ __forceinline__ void split_fp16(float x, __half& h, __half& l) {
    h = __float2half_rn(x);
    l = __float2half_rn(x - __half2float(h));
}

// ---------------- K0: fused sigmoid + scale + parallel CIF scan -------------
__global__ void __launch_bounds__(512) alpha_scan_kernel(
    const float* __restrict__ af, const int* __restrict__ nt,
    float* __restrict__ out, int pred_off)
{
    int b = blockIdx.x, tid = threadIdx.x;
    int lane = tid & 31, wid = tid >> 5;
    int t0 = tid * 3;
    float a[3];
    float sum = 0.f;
#pragma unroll
    for (int j = 0; j < 3; j++) {
        int t = t0 + j;
        if (t < Tq) {
            float x = af[((size_t)b*Tq + t)*Hq + (Hq-1)];
            float s = 1.f / (1.f + expf(-x));
            a[j] = s; sum += s;
        } else a[j] = 0.f;
    }
    __shared__ float red[16];
    __shared__ float wsum[16];
    __shared__ float s_scale, s_Sp_last, s_Sc_last;
    float r = sum;
#pragma unroll
    for (int o = 16; o; o >>= 1) r += __shfl_xor_sync(0xffffffffu, r, o);
    if (lane == 0) red[wid] = r;
    __syncthreads();
    if (tid == 0) {
        float tot = 0.f;
#pragma unroll
        for (int i = 0; i < 16; i++) tot += red[i];
        out[pred_off + b] = tot;
        s_scale = (float)nt[b] / tot;
    }
    __syncthreads();
    float sc = s_scale;
#pragma unroll
    for (int j = 0; j < 3; j++) a[j] *= sc;

    float tot3 = a[0] + a[1] + a[2];
    float inc = tot3;
#pragma unroll
    for (int o = 1; o < 32; o <<= 1) {
        float v = __shfl_up_sync(0xffffffffu, inc, o);
        if (lane >= o) inc += v;
    }
    if (lane == 31) wsum[wid] = inc;
    __syncthreads();
    if (wid == 0) {
        float v = (lane < 16) ? wsum[lane] : 0.f;
#pragma unroll
        for (int o = 1; o < 16; o <<= 1) {
            float u = __shfl_up_sync(0xffffffffu, v, o);
            if (lane >= o) v += u;
        }
        if (lane < 16) wsum[lane] = v;
    }
    __syncthreads();
    float excl = inc - tot3 + (wid ? wsum[wid-1] : 0.f);

    int nm1 = nt[b] - 1;
    int*   pt  = g_pair_t + b*2*Tq;
    float* pw  = g_pair_w + b*2*Tq;
    int*   off = g_off    + b*(Mq+1);

    float Sp = excl;
#pragma unroll
    for (int j = 0; j < 3; j++) {
        int t = t0 + j;
        if (t < Tq) {
            float Sc = Sp + a[j];
            if (t == Tq - 1) { s_Sp_last = Sp; s_Sc_last = Sc; }
            int Fp = (int)Sp;
            int Fc = (int)Sc;
            int p = t + Fp;
            if (Fc > Fp) {
                pt[p] = t; pw[p] = 1.0f + (float)Fp - Sp;       // need
                if (Fp < nm1) off[Fp + 1] = p + 1;
                if (t < Tq - 1) { pt[p+1] = t; pw[p+1] = Sc - (float)Fc; }  // rem
            } else {
                pt[p] = t; pw[p] = a[j];
            }
            Sp = Sc;
        }
    }
    if (tid == 0) off[0] = 0;
    __syncthreads();
    int Ftot  = (int)s_Sc_last;
    int Fprev = (int)s_Sp_last;
    int lastfire = (Ftot > Fprev) ? 1 : 0;
    int cnt = Tq + Ftot - lastfire;
    int A = (Ftot < nm1) ? Ftot : nm1;
    for (int m = A + 1 + tid; m <= Mq; m += 512) off[m] = cnt;
}

// ---------------- K2: gather -> hi/lo fp16 ----------------------------------
__global__ void __launch_bounds__(256) gather_kernel(const float* __restrict__ af)
{
    int r = blockIdx.x;
    int b = r / Mq, m = r % Mq;
    int tid = threadIdx.x;
    int s = g_off[b*(Mq+1) + m];
    int e = g_off[b*(Mq+1) + m + 1];
    float acc[5] = {0.f, 0.f, 0.f, 0.f, 0.f};
    for (int p = s; p < e; p++) {
        int   t = g_pair_t[b*2*Tq + p];
        float w = g_pair_w[b*2*Tq + p];
        const float* row = af + ((size_t)b*Tq + t)*Hq;
#pragma unroll
        for (int i = 0; i < 5; i++) {
            int d = tid + i*256;
            if (d < Dq) acc[i] = fmaf(w, row[d], acc[i]);
        }
    }
#pragma unroll
    for (int i = 0; i < 5; i++) {
        int d = tid + i*256;
        float x = (d < Dq) ? acc[i] : 0.f;
        __half h, l; split_fp16(x, h, l);
        g_Ahi[(size_t)r*Hq + d] = h;
        g_Alo[(size_t)r*Hq + d] = l;
    }
}

// ---------------- K3: transpose weights -> [N][1280] fp16 -------------------
__global__ void convw_kernel(const float* __restrict__ W,
                             __half* __restrict__ o, int K, int N)
{
    __shared__ float t[32][33];
    int n0 = blockIdx.x*32, k0 = blockIdx.y*32;
    int tx = threadIdx.x, ty = threadIdx.y;
#pragma unroll
    for (int j = 0; j < 32; j += 8) {
        int k = k0 + ty + j;
        t[ty+j][tx] = (k < K) ? W[(size_t)k*N + n0 + tx] : 0.f;
    }
    __syncthreads();
#pragma unroll
    for (int j = 0; j < 32; j += 8) {
        int n = n0 + ty + j;
        o[(size_t)n*Hq + k0 + tx] = __float2half_rn(t[tx][ty+j]);
    }
}

// ---------------- warp-MMA GEMM: C[M,N] = A * B^T + bias --------------------
// Block 256x128, 8 warps (4M x 2N, warp tile 64x64), BK=32, double-buffered
// cp.async, ldmatrix.x4 loads. A fp16 hi+lo, B single fp16: 2 MMAs per tile.
__global__ void __launch_bounds__(256, 1) gemm_kernel(
    const __half* __restrict__ Ahi, const __half* __restrict__ Alo,
    const __half* __restrict__ Bw,
    const float* __restrict__ bias, float* __restrict__ C,
    int N, int Mstore)
{
    extern __shared__ uint32_t sm[];      // [2][STAGE_W]
    const int tid = threadIdx.x;
    const int lane = tid & 31, w = tid >> 5;
    const int wm = w >> 1, wn = w & 1;    // wm:0-3 (64 rows each), wn:0-1 (64 cols)
    const int m0 = blockIdx.y * 256, n0 = blockIdx.x * 128;
    const uint32_t sbase = smem_u32(sm);

    // ---- cp.async: 10 chunks/thread/stage. row=tid>>2 (0..63), ch=tid&3.
    const int crow = tid >> 2, cch = tid & 3;
    const __half* pA_h = Ahi + (size_t)(m0 + crow)*Hq + cch*8;
    const __half* pA_l = Alo + (size_t)(m0 + crow)*Hq + cch*8;
    const __half* pB   = Bw  + (size_t)(n0 + crow)*Hq + cch*8;
    const uint32_t drow = (crow*SW + cch*4)*4;   // byte offset of (row,ch)

    // ---- ldmatrix per-lane addresses
    const int a_row = wm*64 + (lane & 15);
    const int a_k8  = (lane >> 4);               // 0/1 -> +16 bytes
    const uint32_t aAddrHi = sbase + (AHI_W + a_row*SW)*4 + a_k8*16;
    const uint32_t aAddrLo = sbase + (ALO_W + a_row*SW)*4 + a_k8*16;
    const int b_n  = wn*64 + (lane & 7) + ((lane >> 4) & 1)*8;
    const int b_k8 = (lane >> 3) & 1;
    const uint32_t bAddr   = sbase + (BW_W + b_n*SW)*4 + b_k8*16;

    float acc[4][8][4];
#pragma unroll
    for (int mt = 0; mt < 4; mt++)
#pragma unroll
        for (int nt = 0; nt < 8; nt++)
#pragma unroll
            for (int i = 0; i < 4; i++) acc[mt][nt][i] = 0.f;

#define COPY_STAGE(kstg, bufofs) do {                                          \
    const size_t kb = (size_t)(kstg)*BK;                                       \
    _Pragma("unroll")                                                          \
    for (int j = 0; j < 4; j++)                                                \
        CP_ASYNC16(sbase + (bufofs) + AHI_W*4 + j*(64*SW*4) + drow,            \
                   pA_h + (size_t)j*64*Hq + kb);                               \
    _Pragma("unroll")                                                          \
    for (int j = 0; j < 4; j++)                                                \
        CP_ASYNC16(sbase + (bufofs) + ALO_W*4 + j*(64*SW*4) + drow,            \
                   pA_l + (size_t)j*64*Hq + kb);                               \
    _Pragma("unroll")                                                          \
    for (int j = 0; j < 2; j++)                                                \
        CP_ASYNC16(sbase + (bufofs) + BW_W*4 + j*(64*SW*4) + drow,             \
                   pB + (size_t)j*64*Hq + kb);                                 \
} while (0)

    // prologue: stage 0 -> buf 0
    COPY_STAGE(0, 0u);
    CP_COMMIT();

    for (int s = 0; s < KSTAGES; s++) {
        const int buf = s & 1;
        const uint32_t bofs = buf * STAGE_B;
        CP_WAIT0();
        __syncthreads();
        if (s + 1 < KSTAGES) {
            COPY_STAGE(s+1, (uint32_t)((buf^1) * STAGE_B));
            CP_COMMIT();
        }
#pragma unroll
        for (int kk = 0; kk < 2; kk++) {
            const uint32_t kofs = bofs + kk*32;    // 16 fp16 = 32 bytes per kstep
            uint32_t ah[4][4], al[4][4], bb[16];
#pragma unroll
            for (int mt = 0; mt < 4; mt++) {
                LDSM_X4(ah[mt][0], ah[mt][1], ah[mt][2], ah[mt][3],
                        aAddrHi + kofs + mt*(16*SW*4));
                LDSM_X4(al[mt][0], al[mt][1], al[mt][2], al[mt][3],
                        aAddrLo + kofs + mt*(16*SW*4));
            }
#pragma unroll
            for (int np = 0; np < 4; np++) {
                LDSM_X4(bb[np*4+0], bb[np*4+1], bb[np*4+2], bb[np*4+3],
                        bAddr + kofs + np*(16*SW*4));
            }
#pragma unroll
            for (int mt = 0; mt < 4; mt++)
#pragma unroll
                for (int nt = 0; nt < 8; nt++) {
                    mma16816(acc[mt][nt], ah[mt], &bb[nt*2]);
                    mma16816(acc[mt][nt], al[mt], &bb[nt*2]);
                }
        }
    }

    // epilogue: row lane/4 (+8), col (lane%4)*2 (+1), add bias
    const int r4 = lane >> 2, c4 = lane & 3;
#pragma unroll
    for (int mt = 0; mt < 4; mt++) {
        int row = m0 + wm*64 + mt*16 + r4;
#pragma unroll
        for (int nt = 0; nt < 8; nt++) {
            int col = n0 + wn*64 + nt*8 + c4*2;
            float bx = bias[col], by = bias[col+1];
            if (row < Mstore) {
                float2 v = make_float2(acc[mt][nt][0] + bx, acc[mt][nt][1] + by);
                *(float2*)(C + (size_t)row*N + col) = v;
            }
            if (row + 8 < Mstore) {
                float2 v = make_float2(acc[mt][nt][2] + bx, acc[mt][nt][3] + by);
                *(float2*)(C + (size_t)(row+8)*N + col) = v;
            }
        }
    }
}

// ---------------- K5: RMSNorm rows of g_t1 -> hi/lo fp16 --------------------
__global__ void __launch_bounds__(256) rmsnorm_kernel(const float* __restrict__ w)
{
    int r = blockIdx.x, tid = threadIdx.x;
    const float* x = g_t1 + (size_t)r*Hq;
    float v[5];
    float ss = 0.f;
#pragma unroll
    for (int i = 0; i < 5; i++) {
        v[i] = x[tid + i*256];
        ss = fmaf(v[i], v[i], ss);
    }
    __shared__ float red[8];
    __shared__ float s_inv;
#pragma unroll
    for (int o = 16; o; o >>= 1) ss += __shfl_xor_sync(0xffffffffu, ss, o);
    if ((tid & 31) == 0) red[tid >> 5] = ss;
    __syncthreads();
    if (tid == 0) {
        float tot = 0.f;
#pragma unroll
        for (int i = 0; i < 8; i++) tot += red[i];
        s_inv = 1.f / sqrtf(tot / (float)Hq + 1e-6f);
    }
    __syncthreads();
    float inv = s_inv;
#pragma unroll
    for (int i = 0; i < 5; i++) {
        int d = tid + i*256;
        float y = v[i] * inv * w[d];
        __half h, l; split_fp16(y, h, l);
        g_H2hi[(size_t)r*Hq + d] = h;
        g_H2lo[(size_t)r*Hq + d] = l;
    }
}

// ---------------- launch ----------------------------------------------------
extern "C" void kernel_launch(void* const* d_in, const int* in_sizes, int n_in,
                              void* d_out, int out_size)
{
    const float* af     = (const float*)d_in[0];
    const int*   nt     = (const int*)  d_in[1];
    const float* rms_w  = (const float*)d_in[2];
    const float* cif_w  = (const float*)d_in[3];
    const float* cif_b  = (const float*)d_in[4];
    const float* text_w = (const float*)d_in[5];
    const float* text_b = (const float*)d_in[6];
    float* out = (float*)d_out;
    int pred_off = out_size - Bq;

    __half *pAhi, *pAlo, *pH2hi, *pH2lo, *pW1, *pW2;
    float* pT1;
    cudaGetSymbolAddress((void**)&pAhi,  g_Ahi);
    cudaGetSymbolAddress((void**)&pAlo,  g_Alo);
    cudaGetSymbolAddress((void**)&pT1,   g_t1);
    cudaGetSymbolAddress((void**)&pH2hi, g_H2hi);
    cudaGetSymbolAddress((void**)&pH2lo, g_H2lo);
    cudaGetSymbolAddress((void**)&pW1,   g_W1);
    cudaGetSymbolAddress((void**)&pW2,   g_W2);

    cudaFuncSetAttribute(gemm_kernel,
                         cudaFuncAttributeMaxDynamicSharedMemorySize, SMEM_GEMM);

    // Order chosen so gemm1 is our 4th launch (lands under ncu -s 5 -c 1).
    convw_kernel<<<dim3(Hq/32,   Hq/32), dim3(32,8)>>>(cif_w,  pW1, Dq, Hq);
    alpha_scan_kernel<<<Bq, 512>>>(af, nt, out, pred_off);
    gather_kernel<<<ROWS, 256>>>(af);
    // cif_proj: [3072,1280] x [1280,1280]^T + cif_b -> t1 (fp32, all MPAD rows)
    gemm_kernel<<<dim3(Hq/128, MPAD/256), 256, SMEM_GEMM>>>(
        pAhi, pAlo, pW1, cif_b, pT1, Hq, MPAD);
    convw_kernel<<<dim3(OUTq/32, Hq/32), dim3(32,8)>>>(text_w, pW2, Hq, OUTq);
    rmsnorm_kernel<<<MPAD, 256>>>(rms_w);
    // text_proj: [3072,1280] x [4096,1280]^T + text_b -> out (rows < 3000)
    gemm_kernel<<<dim3(OUTq/128, MPAD/256), 256, SMEM_GEMM>>>(
        pH2hi, pH2lo, pW2, text_b, out, OUTq, ROWS);
}

// round 16
// speedup vs baseline: 2.8728x; 1.6023x over previous
#include <cuda_runtime.h>
#include <cuda_fp16.h>
#include <math.h>
#include <stdint.h>

// Problem constants
#define Bq    8
#define Tq    1500
#define Hq    1280
#define Dq    1279
#define Mq    375
#define OUTq  4096
#define MPAD  3072
#define ROWS  (Bq*Mq)       // 3000

// GEMM tiling: block 256x128, 8 warps (4M x 2N), warp tile 64x64, BK=32
// A: single fp16, B: single fp16. 1 MMA per logical tile.
#define BK        32
#define KSTAGES   (Hq/BK)          // 40
#define SW        20               // smem row stride in words (32 data fp16 + 8 pad)
#define AHI_W     0
#define BW_W      (256*SW)         // 5120
#define STAGE_W   (384*SW)         // 7680 words
#define STAGE_B   (STAGE_W*4)      // 30720 bytes
#define SMEM_GEMM (2*STAGE_B)      // 61440 bytes

// ---------------- scratch (device globals: allocation-free) ----------------
__device__ int   g_pair_t[Bq*2*Tq];
__device__ float g_pair_w[Bq*2*Tq];
__device__ int   g_off[Bq*(Mq+1)];

__device__ __align__(128) __half g_Ahi [MPAD*Hq];
__device__ __align__(128) float  g_t1  [MPAD*Hq];
__device__ __align__(128) __half g_H2hi[MPAD*Hq];
__device__ __align__(128) __half g_W1  [Hq*Hq];
__device__ __align__(128) __half g_W2  [OUTq*Hq];

// ---------------- helpers ----------------------------------------------------
__device__ __forceinline__ uint32_t smem_u32(const void* p) {
    uint32_t a;
    asm("{ .reg .u64 t; cvta.to.shared.u64 t, %1; cvt.u32.u64 %0, t; }" : "=r"(a) : "l"(p));
    return a;
}
#define CP_ASYNC16(dst_u32, src_ptr) \
    asm volatile("cp.async.cg.shared.global [%0], [%1], 16;" \
        :: "r"(dst_u32), "l"(src_ptr) : "memory")
#define CP_COMMIT() asm volatile("cp.async.commit_group;" ::: "memory")
#define CP_WAIT0()  asm volatile("cp.async.wait_group 0;" ::: "memory")

#define LDSM_X4(r0,r1,r2,r3, addr) \
    asm volatile("ldmatrix.sync.aligned.m8n8.x4.shared.b16 {%0,%1,%2,%3}, [%4];" \
        : "=r"(r0), "=r"(r1), "=r"(r2), "=r"(r3) : "r"(addr))

__device__ __forceinline__ void mma16816(float* c, const uint32_t* a, const uint32_t* b) {
    asm volatile(
        "mma.sync.aligned.m16n8k16.row.col.f32.f16.f16.f32 "
        "{%0,%1,%2,%3}, {%4,%5,%6,%7}, {%8,%9}, {%0,%1,%2,%3};"
        : "+f"(c[0]), "+f"(c[1]), "+f"(c[2]), "+f"(c[3])
        : "r"(a[0]), "r"(a[1]), "r"(a[2]), "r"(a[3]), "r"(b[0]), "r"(b[1]));
}

// ---------------- K0: fused sigmoid + scale + parallel CIF scan -------------
__global__ void __launch_bounds__(512) alpha_scan_kernel(
    const float* __restrict__ af, const int* __restrict__ nt,
    float* __restrict__ out, int pred_off)
{
    int b = blockIdx.x, tid = threadIdx.x;
    int lane = tid & 31, wid = tid >> 5;
    int t0 = tid * 3;
    float a[3];
    float sum = 0.f;
#pragma unroll
    for (int j = 0; j < 3; j++) {
        int t = t0 + j;
        if (t < Tq) {
            float x = af[((size_t)b*Tq + t)*Hq + (Hq-1)];
            float s = 1.f / (1.f + expf(-x));
            a[j] = s; sum += s;
        } else a[j] = 0.f;
    }
    __shared__ float red[16];
    __shared__ float wsum[16];
    __shared__ float s_scale, s_Sp_last, s_Sc_last;
    float r = sum;
#pragma unroll
    for (int o = 16; o; o >>= 1) r += __shfl_xor_sync(0xffffffffu, r, o);
    if (lane == 0) red[wid] = r;
    __syncthreads();
    if (tid == 0) {
        float tot = 0.f;
#pragma unroll
        for (int i = 0; i < 16; i++) tot += red[i];
        out[pred_off + b] = tot;
        s_scale = (float)nt[b] / tot;
    }
    __syncthreads();
    float sc = s_scale;
#pragma unroll
    for (int j = 0; j < 3; j++) a[j] *= sc;

    float tot3 = a[0] + a[1] + a[2];
    float inc = tot3;
#pragma unroll
    for (int o = 1; o < 32; o <<= 1) {
        float v = __shfl_up_sync(0xffffffffu, inc, o);
        if (lane >= o) inc += v;
    }
    if (lane == 31) wsum[wid] = inc;
    __syncthreads();
    if (wid == 0) {
        float v = (lane < 16) ? wsum[lane] : 0.f;
#pragma unroll
        for (int o = 1; o < 16; o <<= 1) {
            float u = __shfl_up_sync(0xffffffffu, v, o);
            if (lane >= o) v += u;
        }
        if (lane < 16) wsum[lane] = v;
    }
    __syncthreads();
    float excl = inc - tot3 + (wid ? wsum[wid-1] : 0.f);

    int nm1 = nt[b] - 1;
    int*   pt  = g_pair_t + b*2*Tq;
    float* pw  = g_pair_w + b*2*Tq;
    int*   off = g_off    + b*(Mq+1);

    float Sp = excl;
#pragma unroll
    for (int j = 0; j < 3; j++) {
        int t = t0 + j;
        if (t < Tq) {
            float Sc = Sp + a[j];
            if (t == Tq - 1) { s_Sp_last = Sp; s_Sc_last = Sc; }
            int Fp = (int)Sp;
            int Fc = (int)Sc;
            int p = t + Fp;
            if (Fc > Fp) {
                pt[p] = t; pw[p] = 1.0f + (float)Fp - Sp;       // need
                if (Fp < nm1) off[Fp + 1] = p + 1;
                if (t < Tq - 1) { pt[p+1] = t; pw[p+1] = Sc - (float)Fc; }  // rem
            } else {
                pt[p] = t; pw[p] = a[j];
            }
            Sp = Sc;
        }
    }
    if (tid == 0) off[0] = 0;
    __syncthreads();
    int Ftot  = (int)s_Sc_last;
    int Fprev = (int)s_Sp_last;
    int lastfire = (Ftot > Fprev) ? 1 : 0;
    int cnt = Tq + Ftot - lastfire;
    int A = (Ftot < nm1) ? Ftot : nm1;
    for (int m = A + 1 + tid; m <= Mq; m += 512) off[m] = cnt;
}

// ---------------- K2: gather -> fp16 ----------------------------------------
__global__ void __launch_bounds__(256) gather_kernel(const float* __restrict__ af)
{
    int r = blockIdx.x;
    int b = r / Mq, m = r % Mq;
    int tid = threadIdx.x;
    int s = g_off[b*(Mq+1) + m];
    int e = g_off[b*(Mq+1) + m + 1];
    float acc[5] = {0.f, 0.f, 0.f, 0.f, 0.f};
    for (int p = s; p < e; p++) {
        int   t = g_pair_t[b*2*Tq + p];
        float w = g_pair_w[b*2*Tq + p];
        const float* row = af + ((size_t)b*Tq + t)*Hq;
#pragma unroll
        for (int i = 0; i < 5; i++) {
            int d = tid + i*256;
            if (d < Dq) acc[i] = fmaf(w, row[d], acc[i]);
        }
    }
#pragma unroll
    for (int i = 0; i < 5; i++) {
        int d = tid + i*256;
        float x = (d < Dq) ? acc[i] : 0.f;
        g_Ahi[(size_t)r*Hq + d] = __float2half_rn(x);
    }
}

// ---------------- K3: transpose weights -> [N][1280] fp16 -------------------
__global__ void convw_kernel(const float* __restrict__ W,
                             __half* __restrict__ o, int K, int N)
{
    __shared__ float t[32][33];
    int n0 = blockIdx.x*32, k0 = blockIdx.y*32;
    int tx = threadIdx.x, ty = threadIdx.y;
#pragma unroll
    for (int j = 0; j < 32; j += 8) {
        int k = k0 + ty + j;
        t[ty+j][tx] = (k < K) ? W[(size_t)k*N + n0 + tx] : 0.f;
    }
    __syncthreads();
#pragma unroll
    for (int j = 0; j < 32; j += 8) {
        int n = n0 + ty + j;
        o[(size_t)n*Hq + k0 + tx] = __float2half_rn(t[tx][ty+j]);
    }
}

// ---------------- warp-MMA GEMM: C[M,N] = A * B^T + bias --------------------
// Block 256x128, 8 warps (4M x 2N, warp tile 64x64), BK=32, double-buffered
// cp.async, ldmatrix.x4 loads. A and B single fp16: 1 MMA per tile.
__global__ void __launch_bounds__(256, 1) gemm_kernel(
    const __half* __restrict__ Ahi, const __half* __restrict__ Bw,
    const float* __restrict__ bias, float* __restrict__ C,
    int N, int Mstore)
{
    extern __shared__ uint32_t sm[];      // [2][STAGE_W]
    const int tid = threadIdx.x;
    const int lane = tid & 31, w = tid >> 5;
    const int wm = w >> 1, wn = w & 1;    // wm:0-3 (64 rows each), wn:0-1 (64 cols)
    const int m0 = blockIdx.y * 256, n0 = blockIdx.x * 128;
    const uint32_t sbase = smem_u32(sm);

    // ---- cp.async: 6 chunks/thread/stage. row=tid>>2 (0..63), ch=tid&3.
    const int crow = tid >> 2, cch = tid & 3;
    const __half* pA = Ahi + (size_t)(m0 + crow)*Hq + cch*8;
    const __half* pB = Bw  + (size_t)(n0 + crow)*Hq + cch*8;
    const uint32_t drow = (crow*SW + cch*4)*4;   // byte offset of (row,ch)

    // ---- ldmatrix per-lane addresses
    const int a_row = wm*64 + (lane & 15);
    const int a_k8  = (lane >> 4);               // 0/1 -> +16 bytes
    const uint32_t aAddr = sbase + (AHI_W + a_row*SW)*4 + a_k8*16;
    const int b_n  = wn*64 + (lane & 7) + ((lane >> 4) & 1)*8;
    const int b_k8 = (lane >> 3) & 1;
    const uint32_t bAddr = sbase + (BW_W + b_n*SW)*4 + b_k8*16;

    float acc[4][8][4];
#pragma unroll
    for (int mt = 0; mt < 4; mt++)
#pragma unroll
        for (int nt = 0; nt < 8; nt++)
#pragma unroll
            for (int i = 0; i < 4; i++) acc[mt][nt][i] = 0.f;

#define COPY_STAGE(kstg, bufofs) do {                                          \
    const size_t kb = (size_t)(kstg)*BK;                                       \
    _Pragma("unroll")                                                          \
    for (int j = 0; j < 4; j++)                                                \
        CP_ASYNC16(sbase + (bufofs) + AHI_W*4 + j*(64*SW*4) + drow,            \
                   pA + (size_t)j*64*Hq + kb);                                 \
    _Pragma("unroll")                                                          \
    for (int j = 0; j < 2; j++)                                                \
        CP_ASYNC16(sbase + (bufofs) + BW_W*4 + j*(64*SW*4) + drow,             \
                   pB + (size_t)j*64*Hq + kb);                                 \
} while (0)

    // prologue: stage 0 -> buf 0
    COPY_STAGE(0, 0u);
    CP_COMMIT();

    for (int s = 0; s < KSTAGES; s++) {
        const int buf = s & 1;
        const uint32_t bofs = buf * STAGE_B;
        CP_WAIT0();
        __syncthreads();
        if (s + 1 < KSTAGES) {
            COPY_STAGE(s+1, (uint32_t)((buf^1) * STAGE_B));
            CP_COMMIT();
        }
#pragma unroll
        for (int kk = 0; kk < 2; kk++) {
            const uint32_t kofs = bofs + kk*32;    // 16 fp16 = 32 bytes per kstep
            uint32_t aa[4][4], bb[16];
#pragma unroll
            for (int mt = 0; mt < 4; mt++) {
                LDSM_X4(aa[mt][0], aa[mt][1], aa[mt][2], aa[mt][3],
                        aAddr + kofs + mt*(16*SW*4));
            }
#pragma unroll
            for (int np = 0; np < 4; np++) {
                LDSM_X4(bb[np*4+0], bb[np*4+1], bb[np*4+2], bb[np*4+3],
                        bAddr + kofs + np*(16*SW*4));
            }
#pragma unroll
            for (int mt = 0; mt < 4; mt++)
#pragma unroll
                for (int nt = 0; nt < 8; nt++)
                    mma16816(acc[mt][nt], aa[mt], &bb[nt*2]);
        }
    }

    // epilogue: row lane/4 (+8), col (lane%4)*2 (+1), add bias
    const int r4 = lane >> 2, c4 = lane & 3;
#pragma unroll
    for (int mt = 0; mt < 4; mt++) {
        int row = m0 + wm*64 + mt*16 + r4;
#pragma unroll
        for (int nt = 0; nt < 8; nt++) {
            int col = n0 + wn*64 + nt*8 + c4*2;
            float bx = bias[col], by = bias[col+1];
            if (row < Mstore) {
                float2 v = make_float2(acc[mt][nt][0] + bx, acc[mt][nt][1] + by);
                *(float2*)(C + (size_t)row*N + col) = v;
            }
            if (row + 8 < Mstore) {
                float2 v = make_float2(acc[mt][nt][2] + bx, acc[mt][nt][3] + by);
                *(float2*)(C + (size_t)(row+8)*N + col) = v;
            }
        }
    }
}

// ---------------- K5: RMSNorm rows of g_t1 -> fp16 --------------------------
__global__ void __launch_bounds__(256) rmsnorm_kernel(const float* __restrict__ w)
{
    int r = blockIdx.x, tid = threadIdx.x;
    const float* x = g_t1 + (size_t)r*Hq;
    float v[5];
    float ss = 0.f;
#pragma unroll
    for (int i = 0; i < 5; i++) {
        v[i] = x[tid + i*256];
        ss = fmaf(v[i], v[i], ss);
    }
    __shared__ float red[8];
    __shared__ float s_inv;
#pragma unroll
    for (int o = 16; o; o >>= 1) ss += __shfl_xor_sync(0xffffffffu, ss, o);
    if ((tid & 31) == 0) red[tid >> 5] = ss;
    __syncthreads();
    if (tid == 0) {
        float tot = 0.f;
#pragma unroll
        for (int i = 0; i < 8; i++) tot += red[i];
        s_inv = 1.f / sqrtf(tot / (float)Hq + 1e-6f);
    }
    __syncthreads();
    float inv = s_inv;
#pragma unroll
    for (int i = 0; i < 5; i++) {
        int d = tid + i*256;
        float y = v[i] * inv * w[d];
        g_H2hi[(size_t)r*Hq + d] = __float2half_rn(y);
    }
}

// ---------------- launch ----------------------------------------------------
extern "C" void kernel_launch(void* const* d_in, const int* in_sizes, int n_in,
                              void* d_out, int out_size)
{
    const float* af     = (const float*)d_in[0];
    const int*   nt     = (const int*)  d_in[1];
    const float* rms_w  = (const float*)d_in[2];
    const float* cif_w  = (const float*)d_in[3];
    const float* cif_b  = (const float*)d_in[4];
    const float* text_w = (const float*)d_in[5];
    const float* text_b = (const float*)d_in[6];
    float* out = (float*)d_out;
    int pred_off = out_size - Bq;

    __half *pAhi, *pH2hi, *pW1, *pW2;
    float* pT1;
    cudaGetSymbolAddress((void**)&pAhi,  g_Ahi);
    cudaGetSymbolAddress((void**)&pT1,   g_t1);
    cudaGetSymbolAddress((void**)&pH2hi, g_H2hi);
    cudaGetSymbolAddress((void**)&pW1,   g_W1);
    cudaGetSymbolAddress((void**)&pW2,   g_W2);

    cudaFuncSetAttribute(gemm_kernel,
                         cudaFuncAttributeMaxDynamicSharedMemorySize, SMEM_GEMM);

    // Order chosen so gemm1 is our 4th launch (lands under ncu -s 5 -c 1).
    convw_kernel<<<dim3(Hq/32,   Hq/32), dim3(32,8)>>>(cif_w,  pW1, Dq, Hq);
    alpha_scan_kernel<<<Bq, 512>>>(af, nt, out, pred_off);
    gather_kernel<<<ROWS, 256>>>(af);
    // cif_proj: [3072,1280] x [1280,1280]^T + cif_b -> t1 (fp32, all MPAD rows)
    gemm_kernel<<<dim3(Hq/128, MPAD/256), 256, SMEM_GEMM>>>(
        pAhi, pW1, cif_b, pT1, Hq, MPAD);
    convw_kernel<<<dim3(OUTq/32, Hq/32), dim3(32,8)>>>(text_w, pW2, Hq, OUTq);
    rmsnorm_kernel<<<MPAD, 256>>>(rms_w);
    // text_proj: [3072,1280] x [4096,1280]^T + text_b -> out (rows < 3000)
    gemm_kernel<<<dim3(OUTq/128, MPAD/256), 256, SMEM_GEMM>>>(
        pH2hi, pW2, text_b, out, OUTq, ROWS);
}

// round 17
// speedup vs baseline: 3.0543x; 1.0632x over previous
#include <cuda_runtime.h>
#include <cuda_fp16.h>
#include <math.h>
#include <stdint.h>

// Problem constants
#define Bq    8
#define Tq    1500
#define Hq    1280
#define Dq    1279
#define Mq    375
#define OUTq  4096
#define MPAD  3072
#define ROWS  (Bq*Mq)       // 3000

// GEMM tiling: block 256x128, 8 warps (4M x 2N), warp tile 64x64, BK=64
// A: single fp16, B: single fp16. 1 MMA per logical tile.
#define BK        64
#define KSTAGES   (Hq/BK)          // 20
#define SW        36               // smem row stride in words (64 data fp16 + 16B pad)
#define AHI_W     0
#define BW_W      (256*SW)         // 9216
#define STAGE_W   (384*SW)         // 13824 words
#define STAGE_B   (STAGE_W*4)      // 55296 bytes
#define SMEM_GEMM (2*STAGE_B)      // 110592 bytes

// ---------------- scratch (device globals: allocation-free) ----------------
__device__ int   g_pair_t[Bq*2*Tq];
__device__ float g_pair_w[Bq*2*Tq];
__device__ int   g_off[Bq*(Mq+1)];

__device__ __align__(128) __half g_Ahi [MPAD*Hq];
__device__ __align__(128) float  g_t1  [MPAD*Hq];
__device__ __align__(128) __half g_H2hi[MPAD*Hq];
__device__ __align__(128) __half g_W1  [Hq*Hq];
__device__ __align__(128) __half g_W2  [OUTq*Hq];

// ---------------- helpers ----------------------------------------------------
__device__ __forceinline__ uint32_t smem_u32(const void* p) {
    uint32_t a;
    asm("{ .reg .u64 t; cvta.to.shared.u64 t, %1; cvt.u32.u64 %0, t; }" : "=r"(a) : "l"(p));
    return a;
}
#define CP_ASYNC16(dst_u32, src_ptr) \
    asm volatile("cp.async.cg.shared.global [%0], [%1], 16;" \
        :: "r"(dst_u32), "l"(src_ptr) : "memory")
#define CP_COMMIT() asm volatile("cp.async.commit_group;" ::: "memory")
#define CP_WAIT0()  asm volatile("cp.async.wait_group 0;" ::: "memory")

#define LDSM_X4(r0,r1,r2,r3, addr) \
    asm volatile("ldmatrix.sync.aligned.m8n8.x4.shared.b16 {%0,%1,%2,%3}, [%4];" \
        : "=r"(r0), "=r"(r1), "=r"(r2), "=r"(r3) : "r"(addr))

__device__ __forceinline__ void mma16816(float* c, const uint32_t* a, const uint32_t* b) {
    asm volatile(
        "mma.sync.aligned.m16n8k16.row.col.f32.f16.f16.f32 "
        "{%0,%1,%2,%3}, {%4,%5,%6,%7}, {%8,%9}, {%0,%1,%2,%3};"
        : "+f"(c[0]), "+f"(c[1]), "+f"(c[2]), "+f"(c[3])
        : "r"(a[0]), "r"(a[1]), "r"(a[2]), "r"(a[3]), "r"(b[0]), "r"(b[1]));
}

// ---------------- K0: fused sigmoid + scale + parallel CIF scan -------------
__global__ void __launch_bounds__(512) alpha_scan_kernel(
    const float* __restrict__ af, const int* __restrict__ nt,
    float* __restrict__ out, int pred_off)
{
    int b = blockIdx.x, tid = threadIdx.x;
    int lane = tid & 31, wid = tid >> 5;
    int t0 = tid * 3;
    float a[3];
    float sum = 0.f;
#pragma unroll
    for (int j = 0; j < 3; j++) {
        int t = t0 + j;
        if (t < Tq) {
            float x = af[((size_t)b*Tq + t)*Hq + (Hq-1)];
            float s = 1.f / (1.f + expf(-x));
            a[j] = s; sum += s;
        } else a[j] = 0.f;
    }
    __shared__ float red[16];
    __shared__ float wsum[16];
    __shared__ float s_scale, s_Sp_last, s_Sc_last;
    float r = sum;
#pragma unroll
    for (int o = 16; o; o >>= 1) r += __shfl_xor_sync(0xffffffffu, r, o);
    if (lane == 0) red[wid] = r;
    __syncthreads();
    if (tid == 0) {
        float tot = 0.f;
#pragma unroll
        for (int i = 0; i < 16; i++) tot += red[i];
        out[pred_off + b] = tot;
        s_scale = (float)nt[b] / tot;
    }
    __syncthreads();
    float sc = s_scale;
#pragma unroll
    for (int j = 0; j < 3; j++) a[j] *= sc;

    float tot3 = a[0] + a[1] + a[2];
    float inc = tot3;
#pragma unroll
    for (int o = 1; o < 32; o <<= 1) {
        float v = __shfl_up_sync(0xffffffffu, inc, o);
        if (lane >= o) inc += v;
    }
    if (lane == 31) wsum[wid] = inc;
    __syncthreads();
    if (wid == 0) {
        float v = (lane < 16) ? wsum[lane] : 0.f;
#pragma unroll
        for (int o = 1; o < 16; o <<= 1) {
            float u = __shfl_up_sync(0xffffffffu, v, o);
            if (lane >= o) v += u;
        }
        if (lane < 16) wsum[lane] = v;
    }
    __syncthreads();
    float excl = inc - tot3 + (wid ? wsum[wid-1] : 0.f);

    int nm1 = nt[b] - 1;
    int*   pt  = g_pair_t + b*2*Tq;
    float* pw  = g_pair_w + b*2*Tq;
    int*   off = g_off    + b*(Mq+1);

    float Sp = excl;
#pragma unroll
    for (int j = 0; j < 3; j++) {
        int t = t0 + j;
        if (t < Tq) {
            float Sc = Sp + a[j];
            if (t == Tq - 1) { s_Sp_last = Sp; s_Sc_last = Sc; }
            int Fp = (int)Sp;
            int Fc = (int)Sc;
            int p = t + Fp;
            if (Fc > Fp) {
                pt[p] = t; pw[p] = 1.0f + (float)Fp - Sp;       // need
                if (Fp < nm1) off[Fp + 1] = p + 1;
                if (t < Tq - 1) { pt[p+1] = t; pw[p+1] = Sc - (float)Fc; }  // rem
            } else {
                pt[p] = t; pw[p] = a[j];
            }
            Sp = Sc;
        }
    }
    if (tid == 0) off[0] = 0;
    __syncthreads();
    int Ftot  = (int)s_Sc_last;
    int Fprev = (int)s_Sp_last;
    int lastfire = (Ftot > Fprev) ? 1 : 0;
    int cnt = Tq + Ftot - lastfire;
    int A = (Ftot < nm1) ? Ftot : nm1;
    for (int m = A + 1 + tid; m <= Mq; m += 512) off[m] = cnt;
}

// ---------------- K2: gather -> fp16 ----------------------------------------
__global__ void __launch_bounds__(256) gather_kernel(const float* __restrict__ af)
{
    int r = blockIdx.x;
    int b = r / Mq, m = r % Mq;
    int tid = threadIdx.x;
    int s = g_off[b*(Mq+1) + m];
    int e = g_off[b*(Mq+1) + m + 1];
    float acc[5] = {0.f, 0.f, 0.f, 0.f, 0.f};
    for (int p = s; p < e; p++) {
        int   t = g_pair_t[b*2*Tq + p];
        float w = g_pair_w[b*2*Tq + p];
        const float* row = af + ((size_t)b*Tq + t)*Hq;
#pragma unroll
        for (int i = 0; i < 5; i++) {
            int d = tid + i*256;
            if (d < Dq) acc[i] = fmaf(w, row[d], acc[i]);
        }
    }
#pragma unroll
    for (int i = 0; i < 5; i++) {
        int d = tid + i*256;
        float x = (d < Dq) ? acc[i] : 0.f;
        g_Ahi[(size_t)r*Hq + d] = __float2half_rn(x);
    }
}

// ---------------- K3: transpose weights -> [N][1280] fp16 -------------------
__global__ void convw_kernel(const float* __restrict__ W,
                             __half* __restrict__ o, int K, int N)
{
    __shared__ float t[32][33];
    int n0 = blockIdx.x*32, k0 = blockIdx.y*32;
    int tx = threadIdx.x, ty = threadIdx.y;
#pragma unroll
    for (int j = 0; j < 32; j += 8) {
        int k = k0 + ty + j;
        t[ty+j][tx] = (k < K) ? W[(size_t)k*N + n0 + tx] : 0.f;
    }
    __syncthreads();
#pragma unroll
    for (int j = 0; j < 32; j += 8) {
        int n = n0 + ty + j;
        o[(size_t)n*Hq + k0 + tx] = __float2half_rn(t[tx][ty+j]);
    }
}

// ---------------- warp-MMA GEMM: C[M,N] = A * B^T + bias --------------------
// Block 256x128, 8 warps (4M x 2N, warp tile 64x64), BK=64, double-buffered
// cp.async, ldmatrix.x4 loads. A and B single fp16: 1 MMA per tile.
__global__ void __launch_bounds__(256, 1) gemm_kernel(
    const __half* __restrict__ Ahi, const __half* __restrict__ Bw,
    const float* __restrict__ bias, float* __restrict__ C,
    int N, int Mstore)
{
    extern __shared__ uint32_t sm[];      // [2][STAGE_W]
    const int tid = threadIdx.x;
    const int lane = tid & 31, w = tid >> 5;
    const int wm = w >> 1, wn = w & 1;    // wm:0-3 (64 rows each), wn:0-1 (64 cols)
    const int m0 = blockIdx.y * 256, n0 = blockIdx.x * 128;
    const uint32_t sbase = smem_u32(sm);

    // ---- cp.async: 12 chunks/thread/stage. r0=tid>>3 (0..31), ch=tid&7.
    // Rows j*32+r0: j=0..7 -> A rows 0..255; j=8..11 -> B rows 0..127.
    const int r0 = tid >> 3, ch = tid & 7;
    const __half* pA = Ahi + (size_t)(m0 + r0)*Hq + ch*8;
    const __half* pB = Bw  + (size_t)(n0 + r0)*Hq + ch*8;
    const uint32_t drow = (r0*SW + ch*4)*4;      // byte offset of (r0,ch)

    // ---- ldmatrix per-lane addresses
    const int a_row = wm*64 + (lane & 15);
    const int a_k8  = (lane >> 4);               // 0/1 -> +16 bytes
    const uint32_t aAddr = sbase + (AHI_W + a_row*SW)*4 + a_k8*16;
    const int b_n  = wn*64 + (lane & 7) + ((lane >> 4) & 1)*8;
    const int b_k8 = (lane >> 3) & 1;
    const uint32_t bAddr = sbase + (BW_W + b_n*SW)*4 + b_k8*16;

    float acc[4][8][4];
#pragma unroll
    for (int mt = 0; mt < 4; mt++)
#pragma unroll
        for (int nt = 0; nt < 8; nt++)
#pragma unroll
            for (int i = 0; i < 4; i++) acc[mt][nt][i] = 0.f;

#define COPY_STAGE(kstg, bufofs) do {                                          \
    const size_t kb = (size_t)(kstg)*BK;                                       \
    _Pragma("unroll")                                                          \
    for (int j = 0; j < 8; j++)                                                \
        CP_ASYNC16(sbase + (bufofs) + j*(32*SW*4) + drow,                      \
                   pA + (size_t)j*32*Hq + kb);                                 \
    _Pragma("unroll")                                                          \
    for (int j = 0; j < 4; j++)                                                \
        CP_ASYNC16(sbase + (bufofs) + BW_W*4 + j*(32*SW*4) + drow,             \
                   pB + (size_t)j*32*Hq + kb);                                 \
} while (0)

    // prologue: stage 0 -> buf 0
    COPY_STAGE(0, 0u);
    CP_COMMIT();

    for (int s = 0; s < KSTAGES; s++) {
        const int buf = s & 1;
        const uint32_t bofs = buf * STAGE_B;
        CP_WAIT0();
        __syncthreads();
        if (s + 1 < KSTAGES) {
            COPY_STAGE(s+1, (uint32_t)((buf^1) * STAGE_B));
            CP_COMMIT();
        }
#pragma unroll
        for (int kk = 0; kk < 4; kk++) {
            const uint32_t kofs = bofs + kk*32;    // 16 fp16 = 32 bytes per kstep
            uint32_t aa[4][4], bb[16];
#pragma unroll
            for (int mt = 0; mt < 4; mt++) {
                LDSM_X4(aa[mt][0], aa[mt][1], aa[mt][2], aa[mt][3],
                        aAddr + kofs + mt*(16*SW*4));
            }
#pragma unroll
            for (int np = 0; np < 4; np++) {
                LDSM_X4(bb[np*4+0], bb[np*4+1], bb[np*4+2], bb[np*4+3],
                        bAddr + kofs + np*(16*SW*4));
            }
#pragma unroll
            for (int mt = 0; mt < 4; mt++)
#pragma unroll
                for (int nt = 0; nt < 8; nt++)
                    mma16816(acc[mt][nt], aa[mt], &bb[nt*2]);
        }
    }

    // epilogue: row lane/4 (+8), col (lane%4)*2 (+1), add bias
    const int r4 = lane >> 2, c4 = lane & 3;
#pragma unroll
    for (int mt = 0; mt < 4; mt++) {
        int row = m0 + wm*64 + mt*16 + r4;
#pragma unroll
        for (int nt = 0; nt < 8; nt++) {
            int col = n0 + wn*64 + nt*8 + c4*2;
            float bx = bias[col], by = bias[col+1];
            if (row < Mstore) {
                float2 v = make_float2(acc[mt][nt][0] + bx, acc[mt][nt][1] + by);
                *(float2*)(C + (size_t)row*N + col) = v;
            }
            if (row + 8 < Mstore) {
                float2 v = make_float2(acc[mt][nt][2] + bx, acc[mt][nt][3] + by);
                *(float2*)(C + (size_t)(row+8)*N + col) = v;
            }
        }
    }
}

// ---------------- K5: RMSNorm rows of g_t1 -> fp16 --------------------------
__global__ void __launch_bounds__(256) rmsnorm_kernel(const float* __restrict__ w)
{
    int r = blockIdx.x, tid = threadIdx.x;
    const float* x = g_t1 + (size_t)r*Hq;
    float v[5];
    float ss = 0.f;
#pragma unroll
    for (int i = 0; i < 5; i++) {
        v[i] = x[tid + i*256];
        ss = fmaf(v[i], v[i], ss);
    }
    __shared__ float red[8];
    __shared__ float s_inv;
#pragma unroll
    for (int o = 16; o; o >>= 1) ss += __shfl_xor_sync(0xffffffffu, ss, o);
    if ((tid & 31) == 0) red[tid >> 5] = ss;
    __syncthreads();
    if (tid == 0) {
        float tot = 0.f;
#pragma unroll
        for (int i = 0; i < 8; i++) tot += red[i];
        s_inv = 1.f / sqrtf(tot / (float)Hq + 1e-6f);
    }
    __syncthreads();
    float inv = s_inv;
#pragma unroll
    for (int i = 0; i < 5; i++) {
        int d = tid + i*256;
        float y = v[i] * inv * w[d];
        g_H2hi[(size_t)r*Hq + d] = __float2half_rn(y);
    }
}

// ---------------- launch ----------------------------------------------------
extern "C" void kernel_launch(void* const* d_in, const int* in_sizes, int n_in,
                              void* d_out, int out_size)
{
    const float* af     = (const float*)d_in[0];
    const int*   nt     = (const int*)  d_in[1];
    const float* rms_w  = (const float*)d_in[2];
    const float* cif_w  = (const float*)d_in[3];
    const float* cif_b  = (const float*)d_in[4];
    const float* text_w = (const float*)d_in[5];
    const float* text_b = (const float*)d_in[6];
    float* out = (float*)d_out;
    int pred_off = out_size - Bq;

    __half *pAhi, *pH2hi, *pW1, *pW2;
    float* pT1;
    cudaGetSymbolAddress((void**)&pAhi,  g_Ahi);
    cudaGetSymbolAddress((void**)&pT1,   g_t1);
    cudaGetSymbolAddress((void**)&pH2hi, g_H2hi);
    cudaGetSymbolAddress((void**)&pW1,   g_W1);
    cudaGetSymbolAddress((void**)&pW2,   g_W2);

    cudaFuncSetAttribute(gemm_kernel,
                         cudaFuncAttributeMaxDynamicSharedMemorySize, SMEM_GEMM);

    // Order chosen so gemm1 is our 4th launch (lands under ncu -s 5 -c 1).
    convw_kernel<<<dim3(Hq/32,   Hq/32), dim3(32,8)>>>(cif_w,  pW1, Dq, Hq);
    alpha_scan_kernel<<<Bq, 512>>>(af, nt, out, pred_off);
    gather_kernel<<<ROWS, 256>>>(af);
    // cif_proj: [3072,1280] x [1280,1280]^T + cif_b -> t1 (fp32, all MPAD rows)
    gemm_kernel<<<dim3(Hq/128, MPAD/256), 256, SMEM_GEMM>>>(
        pAhi, pW1, cif_b, pT1, Hq, MPAD);
    convw_kernel<<<dim3(OUTq/32, Hq/32), dim3(32,8)>>>(text_w, pW2, Hq, OUTq);
    rmsnorm_kernel<<<MPAD, 256>>>(rms_w);
    // text_proj: [3072,1280] x [4096,1280]^T + text_b -> out (rows < 3000)
    gemm_kernel<<<dim3(OUTq/128, MPAD/256), 256, SMEM_GEMM>>>(
        pH2hi, pW2, text_b, out, OUTq, ROWS);
}